// round 1
// baseline (speedup 1.0000x reference)
#include <cuda_runtime.h>
#include <stdint.h>

#define NN 100000
#define DD 128
#define EE 1600000

// ---------------- scratch (device globals: no allocation allowed) ----------
__device__ __align__(16) float g_M[(size_t)NN*DD];   // mean-aggregated features
__device__ __align__(16) float g_Y[(size_t)NN*DD];   // pre-BN linear output
__device__ __align__(16) float g_H[(size_t)NN*DD];   // post-activation features
__device__ __align__(16) float g_PS[(size_t)NN*32];  // layer3: [P(16) | S(16)] per row
__device__ int g_deg[NN];
__device__ int g_rowptr[NN+1];
__device__ int g_cursor[NN];
__device__ int g_csrsrc[EE];
__device__ __align__(16) float g_colsum[DD];
__device__ __align__(16) float g_colsq[DD];
__device__ __align__(16) float g_scale[DD];
__device__ __align__(16) float g_shift[DD];
__device__ uint2 g_keys[2];

// ---------------- threefry2x32 (matches JAX) ------------------------------
__device__ __forceinline__ uint32_t rotl32(uint32_t v, int d) {
    return (v << d) | (v >> (32 - d));
}

__device__ __forceinline__ uint2 threefry(uint32_t k0, uint32_t k1,
                                          uint32_t x0, uint32_t x1) {
    uint32_t k2 = k0 ^ k1 ^ 0x1BD11BDAu;
    x0 += k0; x1 += k1;
#define TFR(a,b,c,d) \
    x0+=x1; x1=rotl32(x1,a); x1^=x0; \
    x0+=x1; x1=rotl32(x1,b); x1^=x0; \
    x0+=x1; x1=rotl32(x1,c); x1^=x0; \
    x0+=x1; x1=rotl32(x1,d); x1^=x0;
    TFR(13,15,26,6)   x0+=k1; x1+=k2+1u;
    TFR(17,29,16,24)  x0+=k2; x1+=k0+2u;
    TFR(13,15,26,6)   x0+=k0; x1+=k1+3u;
    TFR(17,29,16,24)  x0+=k1; x1+=k2+4u;
    TFR(13,15,26,6)   x0+=k2; x1+=k0+5u;
#undef TFR
    return make_uint2(x0, x1);
}

// jax.random.key(42) -> (0,42); partitionable fold-like split:
// key_i = threefry(key, hi=0, lo=i)
__global__ void k_keys() {
    if (threadIdx.x == 0) {
        g_keys[0] = threefry(0u, 42u, 0u, 0u);
        g_keys[1] = threefry(0u, 42u, 0u, 1u);
    }
}

// ---------------- CSR build ------------------------------------------------
__global__ void k_zero_deg() {
    int i = blockIdx.x * blockDim.x + threadIdx.x;
    if (i < NN) g_deg[i] = 0;
}

__global__ void k_deg(const int* __restrict__ dst) {
    int e = blockIdx.x * blockDim.x + threadIdx.x;
    if (e < EE) atomicAdd(&g_deg[dst[e]], 1);
}

__global__ void k_scan() {  // single-block exclusive scan of g_deg -> g_rowptr
    __shared__ int sh[1024];
    __shared__ int carry;
    if (threadIdx.x == 0) carry = 0;
    __syncthreads();
    for (int base = 0; base < NN; base += 1024) {
        int i = base + threadIdx.x;
        int v = (i < NN) ? g_deg[i] : 0;
        sh[threadIdx.x] = v;
        __syncthreads();
        for (int off = 1; off < 1024; off <<= 1) {
            int t = (threadIdx.x >= off) ? sh[threadIdx.x - off] : 0;
            __syncthreads();
            sh[threadIdx.x] += t;
            __syncthreads();
        }
        int excl = sh[threadIdx.x] - v + carry;
        if (i < NN) { g_rowptr[i] = excl; g_cursor[i] = excl; }
        __syncthreads();
        if (threadIdx.x == 0) carry += sh[1023];
        __syncthreads();
    }
    if (threadIdx.x == 0) g_rowptr[NN] = carry;
}

__global__ void k_fill(const int* __restrict__ src, const int* __restrict__ dst) {
    int e = blockIdx.x * blockDim.x + threadIdx.x;
    if (e < EE) {
        int p = atomicAdd(&g_cursor[dst[e]], 1);
        g_csrsrc[p] = src[e];
    }
}

// ---------------- mean aggregation (warp per node) ------------------------
__global__ void k_agg(const float* __restrict__ X) {
    int w = (blockIdx.x * blockDim.x + threadIdx.x) >> 5;
    int lane = threadIdx.x & 31;
    if (w >= NN) return;
    int s0 = g_rowptr[w], s1 = g_rowptr[w + 1];
    float4 acc = make_float4(0.f, 0.f, 0.f, 0.f);
    int e = s0;
    for (; e + 4 <= s1; e += 4) {
        int a = g_csrsrc[e], b = g_csrsrc[e+1], c = g_csrsrc[e+2], d = g_csrsrc[e+3];
        float4 va = *(const float4*)(X + (size_t)a * DD + lane * 4);
        float4 vb = *(const float4*)(X + (size_t)b * DD + lane * 4);
        float4 vc = *(const float4*)(X + (size_t)c * DD + lane * 4);
        float4 vd = *(const float4*)(X + (size_t)d * DD + lane * 4);
        acc.x += va.x + vb.x + vc.x + vd.x;
        acc.y += va.y + vb.y + vc.y + vd.y;
        acc.z += va.z + vb.z + vc.z + vd.z;
        acc.w += va.w + vb.w + vc.w + vd.w;
    }
    for (; e < s1; e++) {
        int a = g_csrsrc[e];
        float4 va = *(const float4*)(X + (size_t)a * DD + lane * 4);
        acc.x += va.x; acc.y += va.y; acc.z += va.z; acc.w += va.w;
    }
    float inv = 1.f / fmaxf((float)(s1 - s0), 1.f);
    float4 o = make_float4(acc.x * inv, acc.y * inv, acc.z * inv, acc.w * inv);
    *(float4*)(g_M + (size_t)w * DD + lane * 4) = o;
}

// ---------------- dual GEMM: C = A@Wl + B@Wr + bias  (K=256 concat) -------
__global__ __launch_bounds__(256, 2)
void k_gemm(const float* __restrict__ A, const float* __restrict__ B,
            const float* __restrict__ Wl, const float* __restrict__ Wr,
            const float* __restrict__ bias, float* __restrict__ C) {
    __shared__ __align__(16) float As[16][132];
    __shared__ __align__(16) float Ws[16][128];
    int tid = threadIdx.x;
    int row0 = blockIdx.x * 128;
    int ty = tid >> 4, tx = tid & 15;
    float acc[8][8];
#pragma unroll
    for (int i = 0; i < 8; i++)
#pragma unroll
        for (int j = 0; j < 8; j++) acc[i][j] = 0.f;

    for (int k0 = 0; k0 < 256; k0 += 16) {
        const float* Ap = (k0 < 128) ? A : B;
        const float* Wp = (k0 < 128) ? Wl : Wr;
        int kk = k0 & 127;
#pragma unroll
        for (int q = tid; q < 512; q += 256) {
            int r = q >> 2, kq = (q & 3) << 2;
            int grow = row0 + r;
            float4 v = (grow < NN) ? *(const float4*)(Ap + (size_t)grow * DD + kk + kq)
                                   : make_float4(0.f, 0.f, 0.f, 0.f);
            As[kq + 0][r] = v.x; As[kq + 1][r] = v.y;
            As[kq + 2][r] = v.z; As[kq + 3][r] = v.w;
        }
#pragma unroll
        for (int q = tid; q < 512; q += 256) {
            int kr = q >> 5, jq = (q & 31) << 2;
            *(float4*)&Ws[kr][jq] = *(const float4*)(Wp + (size_t)(kk + kr) * DD + jq);
        }
        __syncthreads();
#pragma unroll
        for (int k = 0; k < 16; k++) {
            float af[8], wf[8];
            *(float4*)(af)     = *(const float4*)&As[k][ty * 8];
            *(float4*)(af + 4) = *(const float4*)&As[k][ty * 8 + 4];
            *(float4*)(wf)     = *(const float4*)&Ws[k][tx * 8];
            *(float4*)(wf + 4) = *(const float4*)&Ws[k][tx * 8 + 4];
#pragma unroll
            for (int i = 0; i < 8; i++)
#pragma unroll
                for (int j = 0; j < 8; j++) acc[i][j] += af[i] * wf[j];
        }
        __syncthreads();
    }
    float bf[8];
    *(float4*)bf       = *(const float4*)(bias + tx * 8);
    *(float4*)(bf + 4) = *(const float4*)(bias + tx * 8 + 4);
#pragma unroll
    for (int i = 0; i < 8; i++) {
        int grow = row0 + ty * 8 + i;
        if (grow < NN) {
            float4 o0 = make_float4(acc[i][0] + bf[0], acc[i][1] + bf[1],
                                    acc[i][2] + bf[2], acc[i][3] + bf[3]);
            float4 o1 = make_float4(acc[i][4] + bf[4], acc[i][5] + bf[5],
                                    acc[i][6] + bf[6], acc[i][7] + bf[7]);
            *(float4*)(C + (size_t)grow * DD + tx * 8)     = o0;
            *(float4*)(C + (size_t)grow * DD + tx * 8 + 4) = o1;
        }
    }
}

// ---------------- BN stats -------------------------------------------------
__global__ void k_zero_stats() {
    int i = threadIdx.x;
    g_colsum[i] = 0.f; g_colsq[i] = 0.f;
}

__global__ void k_stats(const float* __restrict__ Y) {
    __shared__ float ss[256], sq[256];
    int col = threadIdx.x & 127, half = threadIdx.x >> 7;
    float s = 0.f, q = 0.f;
    for (int row = blockIdx.x * 2 + half; row < NN; row += gridDim.x * 2) {
        float v = Y[(size_t)row * DD + col];
        s += v; q += v * v;
    }
    ss[threadIdx.x] = s; sq[threadIdx.x] = q;
    __syncthreads();
    if (threadIdx.x < 128) {
        atomicAdd(&g_colsum[col], ss[threadIdx.x] + ss[threadIdx.x + 128]);
        atomicAdd(&g_colsq[col],  sq[threadIdx.x] + sq[threadIdx.x + 128]);
    }
}

__global__ void k_finalize(const float* __restrict__ gamma,
                           const float* __restrict__ beta) {
    int c = threadIdx.x;
    float mu  = g_colsum[c] / (float)NN;
    float var = g_colsq[c] / (float)NN - mu * mu;
    float r = rsqrtf(var + 1e-5f);
    float sc = gamma[c] * r;
    g_scale[c] = sc;
    g_shift[c] = beta[c] - mu * sc;
}

// ---------------- BN apply + ReLU + dropout --------------------------------
// JAX partitionable path: bits(i) = out0 ^ out1 of threefry(key, 0, i);
// keep iff uniform < 0.5 iff top bit of bits == 0; kept values scaled by 2.
__global__ void k_apply(const float* __restrict__ Y, float* __restrict__ H,
                        int keyidx) {
    int t = blockIdx.x * blockDim.x + threadIdx.x;
    int base = t * 4;
    if (base >= NN * DD) return;
    uint2 key = g_keys[keyidx];
    float4 v  = *(const float4*)(Y + base);
    int col0  = base & 127;
    float4 sc = *(const float4*)(g_scale + col0);
    float4 sh = *(const float4*)(g_shift + col0);
    float vv[4]  = {v.x, v.y, v.z, v.w};
    float scv[4] = {sc.x, sc.y, sc.z, sc.w};
    float shv[4] = {sh.x, sh.y, sh.z, sh.w};
    float o[4];
#pragma unroll
    for (int j = 0; j < 4; j++) {
        float val = fmaxf(vv[j] * scv[j] + shv[j], 0.f);
        uint2 r = threefry(key.x, key.y, 0u, (uint32_t)(base + j));
        uint32_t bits = r.x ^ r.y;
        o[j] = (bits & 0x80000000u) ? 0.f : val * 2.f;
    }
    *(float4*)(H + base) = make_float4(o[0], o[1], o[2], o[3]);
}

// ---------------- layer 3: P = h@W3l, S = h@W3r + b3 -----------------------
__global__ void k_gemm3(const float* __restrict__ Hin,
                        const float* __restrict__ W3l,
                        const float* __restrict__ W3r,
                        const float* __restrict__ b3) {
    __shared__ float Ws[128 * 32];
    for (int i = threadIdx.x; i < 128 * 16; i += 256) {
        int k = i >> 4, c = i & 15;
        Ws[k * 32 + c]      = W3l[i];
        Ws[k * 32 + 16 + c] = W3r[i];
    }
    __syncthreads();
    int row = blockIdx.x * 8 + (threadIdx.x >> 5);
    int col = threadIdx.x & 31;
    if (row >= NN) return;
    const float* h = Hin + (size_t)row * DD;
    float acc = 0.f;
#pragma unroll 8
    for (int k = 0; k < 128; k += 4) {
        float4 hv = *(const float4*)(h + k);
        acc += hv.x * Ws[(k + 0) * 32 + col];
        acc += hv.y * Ws[(k + 1) * 32 + col];
        acc += hv.z * Ws[(k + 2) * 32 + col];
        acc += hv.w * Ws[(k + 3) * 32 + col];
    }
    if (col >= 16) acc += b3[col - 16];
    g_PS[(size_t)row * 32 + col] = acc;
}

// out[n][c] = mean_agg(P)[n][c] + S[n][c]
__global__ void k_aggout(float* __restrict__ out) {
    int t = blockIdx.x * blockDim.x + threadIdx.x;
    int node = t >> 4, c = t & 15;
    if (node >= NN) return;
    int s0 = g_rowptr[node], s1 = g_rowptr[node + 1];
    float acc = 0.f;
    int e = s0;
    for (; e + 2 <= s1; e += 2) {
        int a = g_csrsrc[e], b = g_csrsrc[e + 1];
        acc += g_PS[(size_t)a * 32 + c] + g_PS[(size_t)b * 32 + c];
    }
    for (; e < s1; e++) acc += g_PS[(size_t)g_csrsrc[e] * 32 + c];
    out[node * 16 + c] = acc / fmaxf((float)(s1 - s0), 1.f)
                       + g_PS[(size_t)node * 32 + 16 + c];
}

// ---------------- launch ---------------------------------------------------
extern "C" void kernel_launch(void* const* d_in, const int* in_sizes, int n_in,
                              void* d_out, int out_size) {
    const float* x   = (const float*)d_in[0];
    const int*   ei  = (const int*)d_in[1];
    const int*   src = ei;
    const int*   dst = ei + EE;
    const float* W1l = (const float*)d_in[2];
    const float* W1r = (const float*)d_in[3];
    const float* b1  = (const float*)d_in[4];
    const float* g1  = (const float*)d_in[5];
    const float* be1 = (const float*)d_in[6];
    const float* W2l = (const float*)d_in[7];
    const float* W2r = (const float*)d_in[8];
    const float* b2  = (const float*)d_in[9];
    const float* g2  = (const float*)d_in[10];
    const float* be2 = (const float*)d_in[11];
    const float* W3l = (const float*)d_in[12];
    const float* W3r = (const float*)d_in[13];
    const float* b3  = (const float*)d_in[14];
    float* out = (float*)d_out;

    void *pM, *pY, *pH;
    cudaGetSymbolAddress(&pM, g_M);
    cudaGetSymbolAddress(&pY, g_Y);
    cudaGetSymbolAddress(&pH, g_H);

    k_zero_deg<<<(NN + 255) / 256, 256>>>();
    k_keys<<<1, 32>>>();
    k_deg<<<EE / 256, 256>>>(dst);
    k_scan<<<1, 1024>>>();
    k_fill<<<EE / 256, 256>>>(src, dst);

    // layer 1
    k_agg<<<NN / 8, 256>>>(x);
    k_gemm<<<(NN + 127) / 128, 256>>>((const float*)pM, x, W1l, W1r, b1, (float*)pY);
    k_zero_stats<<<1, 128>>>();
    k_stats<<<512, 256>>>((const float*)pY);
    k_finalize<<<1, 128>>>(g1, be1);
    k_apply<<<(NN * DD / 4 + 255) / 256, 256>>>((const float*)pY, (float*)pH, 0);

    // layer 2
    k_agg<<<NN / 8, 256>>>((const float*)pH);
    k_gemm<<<(NN + 127) / 128, 256>>>((const float*)pM, (const float*)pH, W2l, W2r, b2, (float*)pY);
    k_zero_stats<<<1, 128>>>();
    k_stats<<<512, 256>>>((const float*)pY);
    k_finalize<<<1, 128>>>(g2, be2);
    k_apply<<<(NN * DD / 4 + 255) / 256, 256>>>((const float*)pY, (float*)pH, 1);

    // layer 3 (transform-then-aggregate: 8x less aggregation traffic)
    k_gemm3<<<(NN + 7) / 8, 256>>>((const float*)pH, W3l, W3r, b3);
    k_aggout<<<NN * 16 / 256, 256>>>(out);
}

// round 2
// speedup vs baseline: 1.2792x; 1.2792x over previous
#include <cuda_runtime.h>
#include <stdint.h>

#define NN 100000
#define DD 128
#define EE 1600000
#define SCAN_B 98   // ceil(NN/1024)

// ---------------- scratch (device globals: no allocation allowed) ----------
__device__ __align__(16) float g_M[(size_t)NN*DD];   // mean-aggregated features
__device__ __align__(16) float g_Y[(size_t)NN*DD];   // pre-BN linear output
__device__ __align__(16) float g_H[(size_t)NN*DD];   // post-activation features
__device__ __align__(16) float g_PS[(size_t)NN*32];  // layer3: [P(16) | S(16)] per row
__device__ int g_deg[NN];
__device__ int g_rowptr[NN+1];
__device__ int g_cursor[NN];
__device__ int g_csrsrc[EE];
__device__ int g_bsum[SCAN_B];
__device__ int g_boff[SCAN_B];
__device__ __align__(16) float g_colsum[DD];
__device__ __align__(16) float g_colsq[DD];
__device__ __align__(16) float g_scale[DD];
__device__ __align__(16) float g_shift[DD];
__device__ uint2 g_keys[2];

// ---------------- threefry2x32 (matches JAX) ------------------------------
__device__ __forceinline__ uint32_t rotl32(uint32_t v, int d) {
    return (v << d) | (v >> (32 - d));
}

__device__ __forceinline__ uint2 threefry(uint32_t k0, uint32_t k1,
                                          uint32_t x0, uint32_t x1) {
    uint32_t k2 = k0 ^ k1 ^ 0x1BD11BDAu;
    x0 += k0; x1 += k1;
#define TFR(a,b,c,d) \
    x0+=x1; x1=rotl32(x1,a); x1^=x0; \
    x0+=x1; x1=rotl32(x1,b); x1^=x0; \
    x0+=x1; x1=rotl32(x1,c); x1^=x0; \
    x0+=x1; x1=rotl32(x1,d); x1^=x0;
    TFR(13,15,26,6)   x0+=k1; x1+=k2+1u;
    TFR(17,29,16,24)  x0+=k2; x1+=k0+2u;
    TFR(13,15,26,6)   x0+=k0; x1+=k1+3u;
    TFR(17,29,16,24)  x0+=k1; x1+=k2+4u;
    TFR(13,15,26,6)   x0+=k2; x1+=k0+5u;
#undef TFR
    return make_uint2(x0, x1);
}

__global__ void k_keys() {
    if (threadIdx.x == 0) {
        g_keys[0] = threefry(0u, 42u, 0u, 0u);
        g_keys[1] = threefry(0u, 42u, 0u, 1u);
    }
}

// ---------------- CSR build ------------------------------------------------
__global__ void k_zero_deg() {
    int i = blockIdx.x * blockDim.x + threadIdx.x;
    if (i < NN) g_deg[i] = 0;
}

__global__ void k_deg(const int* __restrict__ dst) {
    int e = blockIdx.x * blockDim.x + threadIdx.x;
    if (e < EE) atomicAdd(&g_deg[dst[e]], 1);
}

// phase 1: per-block local exclusive scan; block totals to g_bsum
__global__ void k_scan1() {
    __shared__ int sh[1024];
    int tid = threadIdx.x;
    int i = blockIdx.x * 1024 + tid;
    int v = (i < NN) ? g_deg[i] : 0;
    sh[tid] = v;
    __syncthreads();
    for (int off = 1; off < 1024; off <<= 1) {
        int t = (tid >= off) ? sh[tid - off] : 0;
        __syncthreads();
        sh[tid] += t;
        __syncthreads();
    }
    if (i < NN) g_rowptr[i] = sh[tid] - v;      // local exclusive
    if (tid == 1023) g_bsum[blockIdx.x] = sh[1023];
}

// phase 2: single-block scan of SCAN_B block sums
__global__ void k_scan2() {
    __shared__ int sh[128];
    int tid = threadIdx.x;
    int v = (tid < SCAN_B) ? g_bsum[tid] : 0;
    sh[tid] = v;
    __syncthreads();
    for (int off = 1; off < 128; off <<= 1) {
        int t = (tid >= off) ? sh[tid - off] : 0;
        __syncthreads();
        sh[tid] += t;
        __syncthreads();
    }
    if (tid < SCAN_B) g_boff[tid] = sh[tid] - v;
    if (tid == 127) g_rowptr[NN] = sh[127];
}

// phase 3: add block offsets; init cursor
__global__ void k_scan3() {
    int i = blockIdx.x * blockDim.x + threadIdx.x;
    if (i < NN) {
        int r = g_rowptr[i] + g_boff[i >> 10];
        g_rowptr[i] = r;
        g_cursor[i] = r;
    }
}

__global__ void k_fill(const int* __restrict__ src, const int* __restrict__ dst) {
    int e = blockIdx.x * blockDim.x + threadIdx.x;
    if (e < EE) {
        int p = atomicAdd(&g_cursor[dst[e]], 1);
        g_csrsrc[p] = src[e];
    }
}

// ---------------- mean aggregation (warp per node) ------------------------
__global__ void k_agg(const float* __restrict__ X) {
    int w = (blockIdx.x * blockDim.x + threadIdx.x) >> 5;
    int lane = threadIdx.x & 31;
    if (w >= NN) return;
    int s0 = g_rowptr[w], s1 = g_rowptr[w + 1];
    float4 acc = make_float4(0.f, 0.f, 0.f, 0.f);
    int e = s0;
    for (; e + 4 <= s1; e += 4) {
        int a = g_csrsrc[e], b = g_csrsrc[e+1], c = g_csrsrc[e+2], d = g_csrsrc[e+3];
        float4 va = *(const float4*)(X + (size_t)a * DD + lane * 4);
        float4 vb = *(const float4*)(X + (size_t)b * DD + lane * 4);
        float4 vc = *(const float4*)(X + (size_t)c * DD + lane * 4);
        float4 vd = *(const float4*)(X + (size_t)d * DD + lane * 4);
        acc.x += va.x + vb.x + vc.x + vd.x;
        acc.y += va.y + vb.y + vc.y + vd.y;
        acc.z += va.z + vb.z + vc.z + vd.z;
        acc.w += va.w + vb.w + vc.w + vd.w;
    }
    for (; e < s1; e++) {
        int a = g_csrsrc[e];
        float4 va = *(const float4*)(X + (size_t)a * DD + lane * 4);
        acc.x += va.x; acc.y += va.y; acc.z += va.z; acc.w += va.w;
    }
    float inv = 1.f / fmaxf((float)(s1 - s0), 1.f);
    float4 o = make_float4(acc.x * inv, acc.y * inv, acc.z * inv, acc.w * inv);
    *(float4*)(g_M + (size_t)w * DD + lane * 4) = o;
}

// ---------------- dual GEMM: C = A@Wl + B@Wr + bias, fused BN stats -------
__global__ __launch_bounds__(256, 2)
void k_gemm(const float* __restrict__ A, const float* __restrict__ B,
            const float* __restrict__ Wl, const float* __restrict__ Wr,
            const float* __restrict__ bias, float* __restrict__ C) {
    __shared__ __align__(16) float As[16][132];
    __shared__ __align__(16) float Ws[16][128];
    __shared__ __align__(16) float red[16][128];
    int tid = threadIdx.x;
    int row0 = blockIdx.x * 128;
    int ty = tid >> 4, tx = tid & 15;
    float acc[8][8];
#pragma unroll
    for (int i = 0; i < 8; i++)
#pragma unroll
        for (int j = 0; j < 8; j++) acc[i][j] = 0.f;

    for (int k0 = 0; k0 < 256; k0 += 16) {
        const float* Ap = (k0 < 128) ? A : B;
        const float* Wp = (k0 < 128) ? Wl : Wr;
        int kk = k0 & 127;
#pragma unroll
        for (int q = tid; q < 512; q += 256) {
            int r = q >> 2, kq = (q & 3) << 2;
            int grow = row0 + r;
            float4 v = (grow < NN) ? *(const float4*)(Ap + (size_t)grow * DD + kk + kq)
                                   : make_float4(0.f, 0.f, 0.f, 0.f);
            As[kq + 0][r] = v.x; As[kq + 1][r] = v.y;
            As[kq + 2][r] = v.z; As[kq + 3][r] = v.w;
        }
#pragma unroll
        for (int q = tid; q < 512; q += 256) {
            int kr = q >> 5, jq = (q & 31) << 2;
            *(float4*)&Ws[kr][jq] = *(const float4*)(Wp + (size_t)(kk + kr) * DD + jq);
        }
        __syncthreads();
#pragma unroll
        for (int k = 0; k < 16; k++) {
            float af[8], wf[8];
            *(float4*)(af)     = *(const float4*)&As[k][ty * 8];
            *(float4*)(af + 4) = *(const float4*)&As[k][ty * 8 + 4];
            *(float4*)(wf)     = *(const float4*)&Ws[k][tx * 8];
            *(float4*)(wf + 4) = *(const float4*)&Ws[k][tx * 8 + 4];
#pragma unroll
            for (int i = 0; i < 8; i++)
#pragma unroll
                for (int j = 0; j < 8; j++) acc[i][j] += af[i] * wf[j];
        }
        __syncthreads();
    }
    float bf[8];
    *(float4*)bf       = *(const float4*)(bias + tx * 8);
    *(float4*)(bf + 4) = *(const float4*)(bias + tx * 8 + 4);
    // add bias, write out, accumulate per-thread column partial sums
    float cs[8], cq[8];
#pragma unroll
    for (int j = 0; j < 8; j++) { cs[j] = 0.f; cq[j] = 0.f; }
#pragma unroll
    for (int i = 0; i < 8; i++) {
        int grow = row0 + ty * 8 + i;
        if (grow < NN) {
#pragma unroll
            for (int j = 0; j < 8; j++) {
                float v = acc[i][j] + bf[j];
                acc[i][j] = v;
                cs[j] += v;
                cq[j] += v * v;
            }
            float4 o0 = make_float4(acc[i][0], acc[i][1], acc[i][2], acc[i][3]);
            float4 o1 = make_float4(acc[i][4], acc[i][5], acc[i][6], acc[i][7]);
            *(float4*)(C + (size_t)grow * DD + tx * 8)     = o0;
            *(float4*)(C + (size_t)grow * DD + tx * 8 + 4) = o1;
        }
    }
    // block-level column reduction (16 ty-partials per column), then 1 atomic/col
#pragma unroll
    for (int j = 0; j < 8; j++) red[ty][tx * 8 + j] = cs[j];
    __syncthreads();
    if (tid < 128) {
        float s = 0.f;
#pragma unroll
        for (int t = 0; t < 16; t++) s += red[t][tid];
        atomicAdd(&g_colsum[tid], s);
    }
    __syncthreads();
#pragma unroll
    for (int j = 0; j < 8; j++) red[ty][tx * 8 + j] = cq[j];
    __syncthreads();
    if (tid < 128) {
        float s = 0.f;
#pragma unroll
        for (int t = 0; t < 16; t++) s += red[t][tid];
        atomicAdd(&g_colsq[tid], s);
    }
}

// ---------------- BN stat helpers -----------------------------------------
__global__ void k_zero_stats() {
    int i = threadIdx.x;
    g_colsum[i] = 0.f; g_colsq[i] = 0.f;
}

__global__ void k_finalize(const float* __restrict__ gamma,
                           const float* __restrict__ beta) {
    int c = threadIdx.x;
    float mu  = g_colsum[c] / (float)NN;
    float var = g_colsq[c] / (float)NN - mu * mu;
    float r = rsqrtf(var + 1e-5f);
    float sc = gamma[c] * r;
    g_scale[c] = sc;
    g_shift[c] = beta[c] - mu * sc;
}

// ---------------- BN apply + ReLU + dropout --------------------------------
__global__ void k_apply(const float* __restrict__ Y, float* __restrict__ H,
                        int keyidx) {
    int t = blockIdx.x * blockDim.x + threadIdx.x;
    int base = t * 4;
    if (base >= NN * DD) return;
    uint2 key = g_keys[keyidx];
    float4 v  = *(const float4*)(Y + base);
    int col0  = base & 127;
    float4 sc = *(const float4*)(g_scale + col0);
    float4 sh = *(const float4*)(g_shift + col0);
    float vv[4]  = {v.x, v.y, v.z, v.w};
    float scv[4] = {sc.x, sc.y, sc.z, sc.w};
    float shv[4] = {sh.x, sh.y, sh.z, sh.w};
    float o[4];
#pragma unroll
    for (int j = 0; j < 4; j++) {
        float val = fmaxf(vv[j] * scv[j] + shv[j], 0.f);
        uint2 r = threefry(key.x, key.y, 0u, (uint32_t)(base + j));
        uint32_t bits = r.x ^ r.y;
        o[j] = (bits & 0x80000000u) ? 0.f : val * 2.f;
    }
    *(float4*)(H + base) = make_float4(o[0], o[1], o[2], o[3]);
}

// ---------------- layer 3: P = h@W3l, S = h@W3r + b3 -----------------------
__global__ void k_gemm3(const float* __restrict__ Hin,
                        const float* __restrict__ W3l,
                        const float* __restrict__ W3r,
                        const float* __restrict__ b3) {
    __shared__ float Ws[128 * 32];
    for (int i = threadIdx.x; i < 128 * 16; i += 256) {
        int k = i >> 4, c = i & 15;
        Ws[k * 32 + c]      = W3l[i];
        Ws[k * 32 + 16 + c] = W3r[i];
    }
    __syncthreads();
    int row = blockIdx.x * 8 + (threadIdx.x >> 5);
    int col = threadIdx.x & 31;
    if (row >= NN) return;
    const float* h = Hin + (size_t)row * DD;
    float acc = 0.f;
#pragma unroll 8
    for (int k = 0; k < 128; k += 4) {
        float4 hv = *(const float4*)(h + k);
        acc += hv.x * Ws[(k + 0) * 32 + col];
        acc += hv.y * Ws[(k + 1) * 32 + col];
        acc += hv.z * Ws[(k + 2) * 32 + col];
        acc += hv.w * Ws[(k + 3) * 32 + col];
    }
    if (col >= 16) acc += b3[col - 16];
    g_PS[(size_t)row * 32 + col] = acc;
}

__global__ void k_aggout(float* __restrict__ out) {
    int t = blockIdx.x * blockDim.x + threadIdx.x;
    int node = t >> 4, c = t & 15;
    if (node >= NN) return;
    int s0 = g_rowptr[node], s1 = g_rowptr[node + 1];
    float acc = 0.f;
    int e = s0;
    for (; e + 2 <= s1; e += 2) {
        int a = g_csrsrc[e], b = g_csrsrc[e + 1];
        acc += g_PS[(size_t)a * 32 + c] + g_PS[(size_t)b * 32 + c];
    }
    for (; e < s1; e++) acc += g_PS[(size_t)g_csrsrc[e] * 32 + c];
    out[node * 16 + c] = acc / fmaxf((float)(s1 - s0), 1.f)
                       + g_PS[(size_t)node * 32 + 16 + c];
}

// ---------------- launch ---------------------------------------------------
extern "C" void kernel_launch(void* const* d_in, const int* in_sizes, int n_in,
                              void* d_out, int out_size) {
    const float* x   = (const float*)d_in[0];
    const int*   ei  = (const int*)d_in[1];
    const int*   src = ei;
    const int*   dst = ei + EE;
    const float* W1l = (const float*)d_in[2];
    const float* W1r = (const float*)d_in[3];
    const float* b1  = (const float*)d_in[4];
    const float* g1  = (const float*)d_in[5];
    const float* be1 = (const float*)d_in[6];
    const float* W2l = (const float*)d_in[7];
    const float* W2r = (const float*)d_in[8];
    const float* b2  = (const float*)d_in[9];
    const float* g2  = (const float*)d_in[10];
    const float* be2 = (const float*)d_in[11];
    const float* W3l = (const float*)d_in[12];
    const float* W3r = (const float*)d_in[13];
    const float* b3  = (const float*)d_in[14];
    float* out = (float*)d_out;

    void *pM, *pY, *pH;
    cudaGetSymbolAddress(&pM, g_M);
    cudaGetSymbolAddress(&pY, g_Y);
    cudaGetSymbolAddress(&pH, g_H);

    k_zero_deg<<<(NN + 255) / 256, 256>>>();
    k_keys<<<1, 32>>>();
    k_deg<<<EE / 256, 256>>>(dst);
    k_scan1<<<SCAN_B, 1024>>>();
    k_scan2<<<1, 128>>>();
    k_scan3<<<SCAN_B, 1024>>>();
    k_fill<<<EE / 256, 256>>>(src, dst);

    // layer 1
    k_agg<<<NN / 8, 256>>>(x);
    k_zero_stats<<<1, 128>>>();
    k_gemm<<<(NN + 127) / 128, 256>>>((const float*)pM, x, W1l, W1r, b1, (float*)pY);
    k_finalize<<<1, 128>>>(g1, be1);
    k_apply<<<(NN * DD / 4 + 255) / 256, 256>>>((const float*)pY, (float*)pH, 0);

    // layer 2
    k_agg<<<NN / 8, 256>>>((const float*)pH);
    k_zero_stats<<<1, 128>>>();
    k_gemm<<<(NN + 127) / 128, 256>>>((const float*)pM, (const float*)pH, W2l, W2r, b2, (float*)pY);
    k_finalize<<<1, 128>>>(g2, be2);
    k_apply<<<(NN * DD / 4 + 255) / 256, 256>>>((const float*)pY, (float*)pH, 1);

    // layer 3 (transform-then-aggregate: 8x less aggregation traffic)
    k_gemm3<<<(NN + 7) / 8, 256>>>((const float*)pH, W3l, W3r, b3);
    k_aggout<<<NN * 16 / 256, 256>>>(out);
}

// round 3
// speedup vs baseline: 1.3758x; 1.0755x over previous
#include <cuda_runtime.h>
#include <cuda_bf16.h>
#include <stdint.h>

#define NN 100000
#define DD 128
#define EE 1600000
#define SCAN_B 98   // ceil(NN/1024)

// ---------------- scratch (device globals: no allocation allowed) ----------
__device__ __align__(16) float g_Y[(size_t)NN*DD];   // pre-BN linear output
__device__ __align__(16) float g_H[(size_t)NN*DD];   // post-activation features
__device__ __align__(16) float g_PS[(size_t)NN*32];  // layer3: [P(16) | S(16)]
__device__ __align__(16) __nv_bfloat16 g_Mh[(size_t)NN*DD];  // mean hi
__device__ __align__(16) __nv_bfloat16 g_Ml[(size_t)NN*DD];  // mean lo
__device__ __align__(16) __nv_bfloat16 g_Xh[(size_t)NN*DD];  // x hi
__device__ __align__(16) __nv_bfloat16 g_Xl[(size_t)NN*DD];  // x lo
__device__ __align__(16) __nv_bfloat16 g_Hh[(size_t)NN*DD];  // h hi
__device__ __align__(16) __nv_bfloat16 g_Hl[(size_t)NN*DD];  // h lo
__device__ __align__(16) __nv_bfloat16 g_Wt1[128*768];       // layer1 weights, [n][k]
__device__ __align__(16) __nv_bfloat16 g_Wt2[128*768];       // layer2 weights, [n][k]
__device__ int g_deg[NN];
__device__ int g_rowptr[NN+1];
__device__ int g_cursor[NN];
__device__ int g_csrsrc[EE];
__device__ int g_bsum[SCAN_B];
__device__ int g_boff[SCAN_B];
__device__ __align__(16) float g_colsum[DD];
__device__ __align__(16) float g_colsq[DD];
__device__ __align__(16) float g_scale[DD];
__device__ __align__(16) float g_shift[DD];
__device__ uint2 g_keys[2];

// ---------------- threefry2x32 (matches JAX) ------------------------------
__device__ __forceinline__ uint32_t rotl32(uint32_t v, int d) {
    return (v << d) | (v >> (32 - d));
}

__device__ __forceinline__ uint2 threefry(uint32_t k0, uint32_t k1,
                                          uint32_t x0, uint32_t x1) {
    uint32_t k2 = k0 ^ k1 ^ 0x1BD11BDAu;
    x0 += k0; x1 += k1;
#define TFR(a,b,c,d) \
    x0+=x1; x1=rotl32(x1,a); x1^=x0; \
    x0+=x1; x1=rotl32(x1,b); x1^=x0; \
    x0+=x1; x1=rotl32(x1,c); x1^=x0; \
    x0+=x1; x1=rotl32(x1,d); x1^=x0;
    TFR(13,15,26,6)   x0+=k1; x1+=k2+1u;
    TFR(17,29,16,24)  x0+=k2; x1+=k0+2u;
    TFR(13,15,26,6)   x0+=k0; x1+=k1+3u;
    TFR(17,29,16,24)  x0+=k1; x1+=k2+4u;
    TFR(13,15,26,6)   x0+=k2; x1+=k0+5u;
#undef TFR
    return make_uint2(x0, x1);
}

__global__ void k_keys() {
    if (threadIdx.x == 0) {
        g_keys[0] = threefry(0u, 42u, 0u, 0u);
        g_keys[1] = threefry(0u, 42u, 0u, 1u);
    }
}

// ---------------- CSR build ------------------------------------------------
__global__ void k_zero_deg() {
    int i = blockIdx.x * blockDim.x + threadIdx.x;
    if (i < NN) g_deg[i] = 0;
}

__global__ void k_deg(const int* __restrict__ dst) {
    int e = blockIdx.x * blockDim.x + threadIdx.x;
    if (e < EE) atomicAdd(&g_deg[dst[e]], 1);
}

__global__ void k_scan1() {
    __shared__ int sh[1024];
    int tid = threadIdx.x;
    int i = blockIdx.x * 1024 + tid;
    int v = (i < NN) ? g_deg[i] : 0;
    sh[tid] = v;
    __syncthreads();
    for (int off = 1; off < 1024; off <<= 1) {
        int t = (tid >= off) ? sh[tid - off] : 0;
        __syncthreads();
        sh[tid] += t;
        __syncthreads();
    }
    if (i < NN) g_rowptr[i] = sh[tid] - v;
    if (tid == 1023) g_bsum[blockIdx.x] = sh[1023];
}

__global__ void k_scan2() {
    __shared__ int sh[128];
    int tid = threadIdx.x;
    int v = (tid < SCAN_B) ? g_bsum[tid] : 0;
    sh[tid] = v;
    __syncthreads();
    for (int off = 1; off < 128; off <<= 1) {
        int t = (tid >= off) ? sh[tid - off] : 0;
        __syncthreads();
        sh[tid] += t;
        __syncthreads();
    }
    if (tid < SCAN_B) g_boff[tid] = sh[tid] - v;
    if (tid == 127) g_rowptr[NN] = sh[127];
}

__global__ void k_scan3() {
    int i = blockIdx.x * blockDim.x + threadIdx.x;
    if (i < NN) {
        int r = g_rowptr[i] + g_boff[i >> 10];
        g_rowptr[i] = r;
        g_cursor[i] = r;
    }
}

__global__ void k_fill(const int* __restrict__ src, const int* __restrict__ dst) {
    int e = blockIdx.x * blockDim.x + threadIdx.x;
    if (e < EE) {
        int p = atomicAdd(&g_cursor[dst[e]], 1);
        g_csrsrc[p] = src[e];
    }
}

// ---------------- mean aggregation (warp per node) → bf16 hi/lo -----------
__global__ void k_agg(const float* __restrict__ X) {
    int w = (blockIdx.x * blockDim.x + threadIdx.x) >> 5;
    int lane = threadIdx.x & 31;
    if (w >= NN) return;
    int s0 = g_rowptr[w], s1 = g_rowptr[w + 1];
    float4 acc = make_float4(0.f, 0.f, 0.f, 0.f);
    int e = s0;
    for (; e + 4 <= s1; e += 4) {
        int a = g_csrsrc[e], b = g_csrsrc[e+1], c = g_csrsrc[e+2], d = g_csrsrc[e+3];
        float4 va = *(const float4*)(X + (size_t)a * DD + lane * 4);
        float4 vb = *(const float4*)(X + (size_t)b * DD + lane * 4);
        float4 vc = *(const float4*)(X + (size_t)c * DD + lane * 4);
        float4 vd = *(const float4*)(X + (size_t)d * DD + lane * 4);
        acc.x += va.x + vb.x + vc.x + vd.x;
        acc.y += va.y + vb.y + vc.y + vd.y;
        acc.z += va.z + vb.z + vc.z + vd.z;
        acc.w += va.w + vb.w + vc.w + vd.w;
    }
    for (; e < s1; e++) {
        int a = g_csrsrc[e];
        float4 va = *(const float4*)(X + (size_t)a * DD + lane * 4);
        acc.x += va.x; acc.y += va.y; acc.z += va.z; acc.w += va.w;
    }
    float inv = 1.f / fmaxf((float)(s1 - s0), 1.f);
    float m[4] = {acc.x * inv, acc.y * inv, acc.z * inv, acc.w * inv};
    size_t base = (size_t)w * DD + lane * 4;
#pragma unroll
    for (int j = 0; j < 4; j++) {
        __nv_bfloat16 h = __float2bfloat16(m[j]);
        __nv_bfloat16 l = __float2bfloat16(m[j] - __bfloat162float(h));
        g_Mh[base + j] = h;
        g_Ml[base + j] = l;
    }
}

// ---------------- split x into bf16 hi/lo ----------------------------------
__global__ void k_cvt_x(const float* __restrict__ X) {
    int t = blockIdx.x * blockDim.x + threadIdx.x;
    size_t base = (size_t)t * 4;
    if (base >= (size_t)NN * DD) return;
    float4 v = *(const float4*)(X + base);
    float m[4] = {v.x, v.y, v.z, v.w};
#pragma unroll
    for (int j = 0; j < 4; j++) {
        __nv_bfloat16 h = __float2bfloat16(m[j]);
        __nv_bfloat16 l = __float2bfloat16(m[j] - __bfloat162float(h));
        g_Xh[base + j] = h;
        g_Xl[base + j] = l;
    }
}

// ---------------- build transposed split weights Wt[n][768] ----------------
// logical K rows: [Wl_h | Wl_l | Wl_h | Wr_h | Wr_l | Wr_h]
__global__ void k_cvt_w(const float* __restrict__ Wl, const float* __restrict__ Wr,
                        __nv_bfloat16* __restrict__ Wt) {
    int idx = blockIdx.x * blockDim.x + threadIdx.x;   // 0..98303
    if (idx >= 768 * 128) return;
    int n = idx & 127;
    int rr = idx >> 7;          // 0..767
    int seg = rr >> 7, kk = rr & 127;
    const float* src = (seg < 3) ? Wl : Wr;
    float w = src[kk * 128 + n];
    __nv_bfloat16 h = __float2bfloat16(w);
    __nv_bfloat16 l = __float2bfloat16(w - __bfloat162float(h));
    bool lopart = (seg == 1 || seg == 4);
    Wt[(size_t)n * 768 + rr] = lopart ? l : h;
}

// ---------------- tensor-core GEMM: C = [A-chunks]@Wt^T + bias, fused stats
// K=768 logical: chunks {Mh, Mh, Ml, Bh, Bh, Bl} x 128 cols each.
__global__ __launch_bounds__(256, 2)
void k_gemm_mma(const __nv_bfloat16* __restrict__ Ah,
                const __nv_bfloat16* __restrict__ Al,
                const __nv_bfloat16* __restrict__ Bh,
                const __nv_bfloat16* __restrict__ Bl,
                const __nv_bfloat16* __restrict__ Wt,
                const float* __restrict__ bias,
                float* __restrict__ C) {
    // smem tiles: [128 rows][36 bf16] = [128][18] u32, double-buffered
    __shared__ uint32_t As[2][128 * 18];
    __shared__ uint32_t Bs[2][128 * 18];
    __shared__ float red[256];

    int tid  = threadIdx.x;
    int lane = tid & 31;
    int warp = tid >> 5;
    int wm = warp & 1;          // 2 warps along M (64 each)
    int wn = warp >> 1;         // 4 warps along N (32 each)
    int g  = lane >> 2;
    int t4 = lane & 3;
    int row0 = blockIdx.x * 128;

    float cacc[4][4][4];
#pragma unroll
    for (int i = 0; i < 4; i++)
#pragma unroll
        for (int j = 0; j < 4; j++)
#pragma unroll
            for (int k = 0; k < 4; k++) cacc[i][j][k] = 0.f;

    // ---- load iteration 0 ----
    {
        const __nv_bfloat16* srcA = Ah;  // chunk 0, kc 0
#pragma unroll
        for (int p = 0; p < 2; p++) {
            int q = tid + p * 256;
            int r = q >> 2, c4 = q & 3;
            int grow = row0 + r;
            uint4 va = (grow < NN)
                ? *(const uint4*)(srcA + (size_t)grow * 128 + c4 * 8)
                : make_uint4(0u, 0u, 0u, 0u);
            uint4 vb = *(const uint4*)(Wt + (size_t)r * 768 + c4 * 8);
            uint32_t* dA = &As[0][r * 18 + c4 * 4];
            dA[0] = va.x; dA[1] = va.y; dA[2] = va.z; dA[3] = va.w;
            uint32_t* dB = &Bs[0][r * 18 + c4 * 4];
            dB[0] = vb.x; dB[1] = vb.y; dB[2] = vb.z; dB[3] = vb.w;
        }
    }
    __syncthreads();

    int buf = 0;
    for (int it = 0; it < 24; it++) {
        uint4 pa[2], pb[2];
        bool have = (it + 1) < 24;
        if (have) {
            int nit = it + 1;
            int chunk = nit >> 2;
            int kc = (nit & 3) * 32;
            const __nv_bfloat16* srcA =
                (chunk <= 1) ? Ah : (chunk == 2) ? Al : (chunk <= 4) ? Bh : Bl;
#pragma unroll
            for (int p = 0; p < 2; p++) {
                int q = tid + p * 256;
                int r = q >> 2, c4 = q & 3;
                int grow = row0 + r;
                pa[p] = (grow < NN)
                    ? *(const uint4*)(srcA + (size_t)grow * 128 + kc + c4 * 8)
                    : make_uint4(0u, 0u, 0u, 0u);
                pb[p] = *(const uint4*)(Wt + (size_t)r * 768 + nit * 32 + c4 * 8);
            }
        }
        // ---- compute on buf ----
#pragma unroll
        for (int ks = 0; ks < 2; ks++) {
            uint32_t bf[4][2];
#pragma unroll
            for (int nt = 0; nt < 4; nt++) {
                int nrow = wn * 32 + nt * 8 + g;
                bf[nt][0] = Bs[buf][nrow * 18 + ks * 8 + t4];
                bf[nt][1] = Bs[buf][nrow * 18 + ks * 8 + t4 + 4];
            }
#pragma unroll
            for (int mt = 0; mt < 4; mt++) {
                int mr = wm * 64 + mt * 16 + g;
                uint32_t a0 = As[buf][mr * 18 + ks * 8 + t4];
                uint32_t a1 = As[buf][(mr + 8) * 18 + ks * 8 + t4];
                uint32_t a2 = As[buf][mr * 18 + ks * 8 + t4 + 4];
                uint32_t a3 = As[buf][(mr + 8) * 18 + ks * 8 + t4 + 4];
#pragma unroll
                for (int nt = 0; nt < 4; nt++) {
                    asm volatile(
                        "mma.sync.aligned.m16n8k16.row.col.f32.bf16.bf16.f32 "
                        "{%0,%1,%2,%3}, {%4,%5,%6,%7}, {%8,%9}, {%0,%1,%2,%3};"
                        : "+f"(cacc[mt][nt][0]), "+f"(cacc[mt][nt][1]),
                          "+f"(cacc[mt][nt][2]), "+f"(cacc[mt][nt][3])
                        : "r"(a0), "r"(a1), "r"(a2), "r"(a3),
                          "r"(bf[nt][0]), "r"(bf[nt][1]));
                }
            }
        }
        if (have) {
#pragma unroll
            for (int p = 0; p < 2; p++) {
                int q = tid + p * 256;
                int r = q >> 2, c4 = q & 3;
                uint32_t* dA = &As[buf ^ 1][r * 18 + c4 * 4];
                dA[0] = pa[p].x; dA[1] = pa[p].y; dA[2] = pa[p].z; dA[3] = pa[p].w;
                uint32_t* dB = &Bs[buf ^ 1][r * 18 + c4 * 4];
                dB[0] = pb[p].x; dB[1] = pb[p].y; dB[2] = pb[p].z; dB[3] = pb[p].w;
            }
        }
        __syncthreads();
        buf ^= 1;
    }

    // ---- epilogue: bias, store, column stats ----
    float bias2[4][2];
#pragma unroll
    for (int nt = 0; nt < 4; nt++) {
        int nc = wn * 32 + nt * 8 + 2 * t4;
        bias2[nt][0] = bias[nc];
        bias2[nt][1] = bias[nc + 1];
    }
    float cs[4][2], cq[4][2];
#pragma unroll
    for (int nt = 0; nt < 4; nt++) { cs[nt][0]=0.f; cs[nt][1]=0.f; cq[nt][0]=0.f; cq[nt][1]=0.f; }
#pragma unroll
    for (int mt = 0; mt < 4; mt++) {
        int r0 = row0 + wm * 64 + mt * 16 + g;
        int r1 = r0 + 8;
#pragma unroll
        for (int nt = 0; nt < 4; nt++) {
            int nc = wn * 32 + nt * 8 + 2 * t4;
            if (r0 < NN) {
                float v0 = cacc[mt][nt][0] + bias2[nt][0];
                float v1 = cacc[mt][nt][1] + bias2[nt][1];
                *(float2*)(C + (size_t)r0 * 128 + nc) = make_float2(v0, v1);
                cs[nt][0] += v0; cq[nt][0] += v0 * v0;
                cs[nt][1] += v1; cq[nt][1] += v1 * v1;
            }
            if (r1 < NN) {
                float v2 = cacc[mt][nt][2] + bias2[nt][0];
                float v3 = cacc[mt][nt][3] + bias2[nt][1];
                *(float2*)(C + (size_t)r1 * 128 + nc) = make_float2(v2, v3);
                cs[nt][0] += v2; cq[nt][0] += v2 * v2;
                cs[nt][1] += v3; cq[nt][1] += v3 * v3;
            }
        }
    }
    red[tid] = 0.f;
    __syncthreads();
#pragma unroll
    for (int nt = 0; nt < 4; nt++) {
        int nc = wn * 32 + nt * 8 + 2 * t4;
        atomicAdd(&red[nc],       cs[nt][0]);
        atomicAdd(&red[nc + 1],   cs[nt][1]);
        atomicAdd(&red[128 + nc],     cq[nt][0]);
        atomicAdd(&red[128 + nc + 1], cq[nt][1]);
    }
    __syncthreads();
    if (tid < 128) {
        atomicAdd(&g_colsum[tid], red[tid]);
        atomicAdd(&g_colsq[tid],  red[128 + tid]);
    }
}

// ---------------- BN stat helpers -----------------------------------------
__global__ void k_zero_stats() {
    int i = threadIdx.x;
    g_colsum[i] = 0.f; g_colsq[i] = 0.f;
}

__global__ void k_finalize(const float* __restrict__ gamma,
                           const float* __restrict__ beta) {
    int c = threadIdx.x;
    float mu  = g_colsum[c] / (float)NN;
    float var = g_colsq[c] / (float)NN - mu * mu;
    float r = rsqrtf(var + 1e-5f);
    float sc = gamma[c] * r;
    g_scale[c] = sc;
    g_shift[c] = beta[c] - mu * sc;
}

// ---------------- BN apply + ReLU + dropout (+ optional bf16 split) -------
__global__ void k_apply(const float* __restrict__ Y, float* __restrict__ H,
                        int keyidx, int writeSplit) {
    int t = blockIdx.x * blockDim.x + threadIdx.x;
    size_t base = (size_t)t * 4;
    if (base >= (size_t)NN * DD) return;
    uint2 key = g_keys[keyidx];
    float4 v  = *(const float4*)(Y + base);
    int col0  = (int)(base & 127);
    float4 sc = *(const float4*)(g_scale + col0);
    float4 sh = *(const float4*)(g_shift + col0);
    float vv[4]  = {v.x, v.y, v.z, v.w};
    float scv[4] = {sc.x, sc.y, sc.z, sc.w};
    float shv[4] = {sh.x, sh.y, sh.z, sh.w};
    float o[4];
#pragma unroll
    for (int j = 0; j < 4; j++) {
        float val = fmaxf(vv[j] * scv[j] + shv[j], 0.f);
        uint2 r = threefry(key.x, key.y, 0u, (uint32_t)(base + j));
        uint32_t bits = r.x ^ r.y;
        o[j] = (bits & 0x80000000u) ? 0.f : val * 2.f;
    }
    *(float4*)(H + base) = make_float4(o[0], o[1], o[2], o[3]);
    if (writeSplit) {
#pragma unroll
        for (int j = 0; j < 4; j++) {
            __nv_bfloat16 h = __float2bfloat16(o[j]);
            __nv_bfloat16 l = __float2bfloat16(o[j] - __bfloat162float(h));
            g_Hh[base + j] = h;
            g_Hl[base + j] = l;
        }
    }
}

// ---------------- layer 3: P = h@W3l, S = h@W3r + b3 -----------------------
__global__ void k_gemm3(const float* __restrict__ Hin,
                        const float* __restrict__ W3l,
                        const float* __restrict__ W3r,
                        const float* __restrict__ b3) {
    __shared__ float Ws[128 * 32];
    for (int i = threadIdx.x; i < 128 * 16; i += 256) {
        int k = i >> 4, c = i & 15;
        Ws[k * 32 + c]      = W3l[i];
        Ws[k * 32 + 16 + c] = W3r[i];
    }
    __syncthreads();
    int row = blockIdx.x * 8 + (threadIdx.x >> 5);
    int col = threadIdx.x & 31;
    if (row >= NN) return;
    const float* h = Hin + (size_t)row * DD;
    float acc = 0.f;
#pragma unroll 8
    for (int k = 0; k < 128; k += 4) {
        float4 hv = *(const float4*)(h + k);
        acc += hv.x * Ws[(k + 0) * 32 + col];
        acc += hv.y * Ws[(k + 1) * 32 + col];
        acc += hv.z * Ws[(k + 2) * 32 + col];
        acc += hv.w * Ws[(k + 3) * 32 + col];
    }
    if (col >= 16) acc += b3[col - 16];
    g_PS[(size_t)row * 32 + col] = acc;
}

__global__ void k_aggout(float* __restrict__ out) {
    int t = blockIdx.x * blockDim.x + threadIdx.x;
    int node = t >> 4, c = t & 15;
    if (node >= NN) return;
    int s0 = g_rowptr[node], s1 = g_rowptr[node + 1];
    float acc = 0.f;
    int e = s0;
    for (; e + 2 <= s1; e += 2) {
        int a = g_csrsrc[e], b = g_csrsrc[e + 1];
        acc += g_PS[(size_t)a * 32 + c] + g_PS[(size_t)b * 32 + c];
    }
    for (; e < s1; e++) acc += g_PS[(size_t)g_csrsrc[e] * 32 + c];
    out[node * 16 + c] = acc / fmaxf((float)(s1 - s0), 1.f)
                       + g_PS[(size_t)node * 32 + 16 + c];
}

// ---------------- launch ---------------------------------------------------
extern "C" void kernel_launch(void* const* d_in, const int* in_sizes, int n_in,
                              void* d_out, int out_size) {
    const float* x   = (const float*)d_in[0];
    const int*   ei  = (const int*)d_in[1];
    const int*   src = ei;
    const int*   dst = ei + EE;
    const float* W1l = (const float*)d_in[2];
    const float* W1r = (const float*)d_in[3];
    const float* b1  = (const float*)d_in[4];
    const float* g1  = (const float*)d_in[5];
    const float* be1 = (const float*)d_in[6];
    const float* W2l = (const float*)d_in[7];
    const float* W2r = (const float*)d_in[8];
    const float* b2  = (const float*)d_in[9];
    const float* g2  = (const float*)d_in[10];
    const float* be2 = (const float*)d_in[11];
    const float* W3l = (const float*)d_in[12];
    const float* W3r = (const float*)d_in[13];
    const float* b3  = (const float*)d_in[14];
    float* out = (float*)d_out;

    void *pY, *pH, *pMh, *pMl, *pXh, *pXl, *pHh, *pHl, *pWt1, *pWt2;
    cudaGetSymbolAddress(&pY,  g_Y);
    cudaGetSymbolAddress(&pH,  g_H);
    cudaGetSymbolAddress(&pMh, g_Mh);
    cudaGetSymbolAddress(&pMl, g_Ml);
    cudaGetSymbolAddress(&pXh, g_Xh);
    cudaGetSymbolAddress(&pXl, g_Xl);
    cudaGetSymbolAddress(&pHh, g_Hh);
    cudaGetSymbolAddress(&pHl, g_Hl);
    cudaGetSymbolAddress(&pWt1, g_Wt1);
    cudaGetSymbolAddress(&pWt2, g_Wt2);

    k_zero_deg<<<(NN + 255) / 256, 256>>>();
    k_keys<<<1, 32>>>();
    k_cvt_w<<<384, 256>>>(W1l, W1r, (__nv_bfloat16*)pWt1);
    k_cvt_w<<<384, 256>>>(W2l, W2r, (__nv_bfloat16*)pWt2);
    k_cvt_x<<<(NN * DD / 4 + 255) / 256, 256>>>(x);
    k_deg<<<EE / 256, 256>>>(dst);
    k_scan1<<<SCAN_B, 1024>>>();
    k_scan2<<<1, 128>>>();
    k_scan3<<<SCAN_B, 1024>>>();
    k_fill<<<EE / 256, 256>>>(src, dst);

    // layer 1
    k_agg<<<NN / 8, 256>>>(x);
    k_zero_stats<<<1, 128>>>();
    k_gemm_mma<<<(NN + 127) / 128, 256>>>(
        (const __nv_bfloat16*)pMh, (const __nv_bfloat16*)pMl,
        (const __nv_bfloat16*)pXh, (const __nv_bfloat16*)pXl,
        (const __nv_bfloat16*)pWt1, b1, (float*)pY);
    k_finalize<<<1, 128>>>(g1, be1);
    k_apply<<<(NN * DD / 4 + 255) / 256, 256>>>((const float*)pY, (float*)pH, 0, 1);

    // layer 2
    k_agg<<<NN / 8, 256>>>((const float*)pH);
    k_zero_stats<<<1, 128>>>();
    k_gemm_mma<<<(NN + 127) / 128, 256>>>(
        (const __nv_bfloat16*)pMh, (const __nv_bfloat16*)pMl,
        (const __nv_bfloat16*)pHh, (const __nv_bfloat16*)pHl,
        (const __nv_bfloat16*)pWt2, b2, (float*)pY);
    k_finalize<<<1, 128>>>(g2, be2);
    k_apply<<<(NN * DD / 4 + 255) / 256, 256>>>((const float*)pY, (float*)pH, 1, 0);

    // layer 3 (transform-then-aggregate)
    k_gemm3<<<(NN + 7) / 8, 256>>>((const float*)pH, W3l, W3r, b3);
    k_aggout<<<NN * 16 / 256, 256>>>(out);
}

// round 8
// speedup vs baseline: 1.3908x; 1.0109x over previous
#include <cuda_runtime.h>
#include <cuda_bf16.h>
#include <stdint.h>

#define NN 100000
#define DD 128
#define EE 1600000
#define SCAN_B 98   // ceil(NN/1024)

// ---------------- scratch (device globals: no allocation allowed) ----------
__device__ __align__(16) float g_Y[(size_t)NN*DD];   // pre-BN linear output
__device__ __align__(16) float g_H[(size_t)NN*DD];   // post-activation features
__device__ __align__(16) float g_PS[(size_t)NN*32];  // layer3: [P(16) | S(16)]
__device__ __align__(16) __nv_bfloat16 g_Mh[(size_t)NN*DD];  // mean hi
__device__ __align__(16) __nv_bfloat16 g_Ml[(size_t)NN*DD];  // mean lo
__device__ __align__(16) __nv_bfloat16 g_Xh[(size_t)NN*DD];  // x hi
__device__ __align__(16) __nv_bfloat16 g_Xl[(size_t)NN*DD];  // x lo
__device__ __align__(16) __nv_bfloat16 g_Hh[(size_t)NN*DD];  // h hi
__device__ __align__(16) __nv_bfloat16 g_Hl[(size_t)NN*DD];  // h lo
__device__ __align__(16) __nv_bfloat16 g_Wt1[128*768];       // layer1 weights, [n][k]
__device__ __align__(16) __nv_bfloat16 g_Wt2[128*768];       // layer2 weights, [n][k]
__device__ int g_deg[NN];
__device__ int g_rowptr[NN+1];
__device__ int g_cursor[NN];
__device__ int g_csrsrc[EE];
__device__ int g_bsum[SCAN_B];
__device__ int g_boff[SCAN_B];
__device__ __align__(16) float g_colsum[DD];
__device__ __align__(16) float g_colsq[DD];
__device__ __align__(16) float g_scale[DD];
__device__ __align__(16) float g_shift[DD];
__device__ uint2 g_keys[2];

// ---------------- threefry2x32 (matches JAX) ------------------------------
__device__ __forceinline__ uint32_t rotl32(uint32_t v, int d) {
    return (v << d) | (v >> (32 - d));
}

__device__ __forceinline__ uint2 threefry(uint32_t k0, uint32_t k1,
                                          uint32_t x0, uint32_t x1) {
    uint32_t k2 = k0 ^ k1 ^ 0x1BD11BDAu;
    x0 += k0; x1 += k1;
#define TFR(a,b,c,d) \
    x0+=x1; x1=rotl32(x1,a); x1^=x0; \
    x0+=x1; x1=rotl32(x1,b); x1^=x0; \
    x0+=x1; x1=rotl32(x1,c); x1^=x0; \
    x0+=x1; x1=rotl32(x1,d); x1^=x0;
    TFR(13,15,26,6)   x0+=k1; x1+=k2+1u;
    TFR(17,29,16,24)  x0+=k2; x1+=k0+2u;
    TFR(13,15,26,6)   x0+=k0; x1+=k1+3u;
    TFR(17,29,16,24)  x0+=k1; x1+=k2+4u;
    TFR(13,15,26,6)   x0+=k2; x1+=k0+5u;
#undef TFR
    return make_uint2(x0, x1);
}

__global__ void k_keys() {
    if (threadIdx.x == 0) {
        g_keys[0] = threefry(0u, 42u, 0u, 0u);
        g_keys[1] = threefry(0u, 42u, 0u, 1u);
    }
}

// ---------------- CSR build ------------------------------------------------
__global__ void k_zero_deg() {
    int i = blockIdx.x * blockDim.x + threadIdx.x;
    if (i < NN) g_deg[i] = 0;
}

__global__ void k_deg(const int* __restrict__ dst) {
    int e = blockIdx.x * blockDim.x + threadIdx.x;
    if (e < EE) atomicAdd(&g_deg[dst[e]], 1);
}

__global__ void k_scan1() {
    __shared__ int sh[1024];
    int tid = threadIdx.x;
    int i = blockIdx.x * 1024 + tid;
    int v = (i < NN) ? g_deg[i] : 0;
    sh[tid] = v;
    __syncthreads();
    for (int off = 1; off < 1024; off <<= 1) {
        int t = (tid >= off) ? sh[tid - off] : 0;
        __syncthreads();
        sh[tid] += t;
        __syncthreads();
    }
    if (i < NN) g_rowptr[i] = sh[tid] - v;
    if (tid == 1023) g_bsum[blockIdx.x] = sh[1023];
}

__global__ void k_scan2() {
    __shared__ int sh[128];
    int tid = threadIdx.x;
    int v = (tid < SCAN_B) ? g_bsum[tid] : 0;
    sh[tid] = v;
    __syncthreads();
    for (int off = 1; off < 128; off <<= 1) {
        int t = (tid >= off) ? sh[tid - off] : 0;
        __syncthreads();
        sh[tid] += t;
        __syncthreads();
    }
    if (tid < SCAN_B) g_boff[tid] = sh[tid] - v;
    if (tid == 127) g_rowptr[NN] = sh[127];
}

__global__ void k_scan3() {
    int i = blockIdx.x * blockDim.x + threadIdx.x;
    if (i < NN) {
        int r = g_rowptr[i] + g_boff[i >> 10];
        g_rowptr[i] = r;
        g_cursor[i] = r;
    }
}

__global__ void k_fill(const int* __restrict__ src, const int* __restrict__ dst) {
    int e = blockIdx.x * blockDim.x + threadIdx.x;
    if (e < EE) {
        int p = atomicAdd(&g_cursor[dst[e]], 1);
        g_csrsrc[p] = src[e];
    }
}

// ---------------- mean aggregation (warp per node) → bf16 hi/lo -----------
__global__ void k_agg(const float* __restrict__ X) {
    int w = (blockIdx.x * blockDim.x + threadIdx.x) >> 5;
    int lane = threadIdx.x & 31;
    if (w >= NN) return;
    int s0 = g_rowptr[w], s1 = g_rowptr[w + 1];
    float4 acc = make_float4(0.f, 0.f, 0.f, 0.f);
    int e = s0;
    for (; e + 4 <= s1; e += 4) {
        int a = g_csrsrc[e], b = g_csrsrc[e+1], c = g_csrsrc[e+2], d = g_csrsrc[e+3];
        float4 va = *(const float4*)(X + (size_t)a * DD + lane * 4);
        float4 vb = *(const float4*)(X + (size_t)b * DD + lane * 4);
        float4 vc = *(const float4*)(X + (size_t)c * DD + lane * 4);
        float4 vd = *(const float4*)(X + (size_t)d * DD + lane * 4);
        acc.x += va.x + vb.x + vc.x + vd.x;
        acc.y += va.y + vb.y + vc.y + vd.y;
        acc.z += va.z + vb.z + vc.z + vd.z;
        acc.w += va.w + vb.w + vc.w + vd.w;
    }
    for (; e < s1; e++) {
        int a = g_csrsrc[e];
        float4 va = *(const float4*)(X + (size_t)a * DD + lane * 4);
        acc.x += va.x; acc.y += va.y; acc.z += va.z; acc.w += va.w;
    }
    float inv = 1.f / fmaxf((float)(s1 - s0), 1.f);
    float m[4] = {acc.x * inv, acc.y * inv, acc.z * inv, acc.w * inv};
    size_t base = (size_t)w * DD + lane * 4;
#pragma unroll
    for (int j = 0; j < 4; j++) {
        __nv_bfloat16 h = __float2bfloat16(m[j]);
        __nv_bfloat16 l = __float2bfloat16(m[j] - __bfloat162float(h));
        g_Mh[base + j] = h;
        g_Ml[base + j] = l;
    }
}

// ---------------- split x into bf16 hi/lo ----------------------------------
__global__ void k_cvt_x(const float* __restrict__ X) {
    int t = blockIdx.x * blockDim.x + threadIdx.x;
    size_t base = (size_t)t * 4;
    if (base >= (size_t)NN * DD) return;
    float4 v = *(const float4*)(X + base);
    float m[4] = {v.x, v.y, v.z, v.w};
#pragma unroll
    for (int j = 0; j < 4; j++) {
        __nv_bfloat16 h = __float2bfloat16(m[j]);
        __nv_bfloat16 l = __float2bfloat16(m[j] - __bfloat162float(h));
        g_Xh[base + j] = h;
        g_Xl[base + j] = l;
    }
}

// ---------------- build transposed split weights Wt[n][768] ----------------
// logical K rows: [Wl_h | Wl_l | Wl_h | Wr_h | Wr_l | Wr_h]
__global__ void k_cvt_w(const float* __restrict__ Wl, const float* __restrict__ Wr,
                        __nv_bfloat16* __restrict__ Wt) {
    int idx = blockIdx.x * blockDim.x + threadIdx.x;   // 0..98303
    if (idx >= 768 * 128) return;
    int n = idx & 127;
    int rr = idx >> 7;          // 0..767
    int seg = rr >> 7, kk = rr & 127;
    const float* src = (seg < 3) ? Wl : Wr;
    float w = src[kk * 128 + n];
    __nv_bfloat16 h = __float2bfloat16(w);
    __nv_bfloat16 l = __float2bfloat16(w - __bfloat162float(h));
    bool lopart = (seg == 1 || seg == 4);
    Wt[(size_t)n * 768 + rr] = lopart ? l : h;
}

// ================= helpers ================================================
__device__ __forceinline__ uint32_t s2u(const void* p) {
    uint32_t a;
    asm("{ .reg .u64 t; cvta.to.shared.u64 t, %1; cvt.u32.u64 %0, t; }"
        : "=r"(a) : "l"(p));
    return a;
}

__device__ __forceinline__ void cp_async16(uint32_t saddr, const void* gaddr, int sz) {
    asm volatile("cp.async.cg.shared.global [%0], [%1], 16, %2;"
                 :: "r"(saddr), "l"(gaddr), "r"(sz));
}

__device__ __forceinline__ void ldsm_x4(uint32_t* r, uint32_t addr) {
    asm volatile("ldmatrix.sync.aligned.m8n8.x4.shared.b16 {%0,%1,%2,%3}, [%4];"
                 : "=r"(r[0]), "=r"(r[1]), "=r"(r[2]), "=r"(r[3]) : "r"(addr));
}

// smem: 3 stages x (A 16KB + B 16KB) + aux
#define ST_BYTES 32768
#define SM_BIAS  98304
#define SM_RS    (98304 + 512)
#define SM_RQ    (98304 + 1024)
#define SM_TOT   (98304 + 1536)

// ---------------- HMMA GEMM: C[128r,128c] = A[128,768] @ Wt^T + bias -------
// 12 K-chunks of 64: A source = {Mh,Mh,Ml,Bh,Bh,Bl}[h>>1], col (h&1)*64
__global__ __launch_bounds__(256, 1)
void k_mma(const __nv_bfloat16* __restrict__ Ah,
           const __nv_bfloat16* __restrict__ Al,
           const __nv_bfloat16* __restrict__ Bh,
           const __nv_bfloat16* __restrict__ Bl,
           const __nv_bfloat16* __restrict__ Wt,
           const float* __restrict__ bias,
           float* __restrict__ C) {
    extern __shared__ __align__(128) char smem[];
    uint32_t su = s2u(smem);
    int tid  = threadIdx.x;
    int lane = tid & 31;
    int warp = tid >> 5;
    int wm = warp & 1;          // 2 warps over M (64 rows)
    int wn = warp >> 1;         // 4 warps over N (32 cols)
    int row0 = blockIdx.x * 128;

    float* biasS = (float*)(smem + SM_BIAS);
    float* redS  = (float*)(smem + SM_RS);
    float* redQ  = (float*)(smem + SM_RQ);
    if (tid < 128) { biasS[tid] = bias[tid]; redS[tid] = 0.f; redQ[tid] = 0.f; }

    // issue one stage's cp.async group (A tile + B tile, 128x64 bf16 each)
    auto issue = [&](int h) {
        int c = h >> 1;
        const __nv_bfloat16* Asrc =
            (c <= 1) ? Ah : (c == 2) ? Al : (c <= 4) ? Bh : Bl;
        int acol = (h & 1) * 64;
        uint32_t sa = su + (h % 3) * ST_BYTES;
        uint32_t sb = sa + 16384;
#pragma unroll
        for (int t = 0; t < 4; t++) {
            int q = tid + t * 256;          // 0..1023
            int r = q >> 3, g = q & 7;
            uint32_t off = (uint32_t)r * 128 + (((uint32_t)g << 4) ^ ((uint32_t)(r & 7) << 4));
            bool live = (row0 + r) < NN;
            const __nv_bfloat16* gA =
                Asrc + (live ? ((size_t)(row0 + r) * 128 + acol + g * 8) : 0);
            cp_async16(sa + off, gA, live ? 16 : 0);
            const __nv_bfloat16* gB = Wt + (size_t)r * 768 + h * 64 + g * 8;
            cp_async16(sb + off, gB, 16);
        }
        asm volatile("cp.async.commit_group;" ::: "memory");
    };

    issue(0);
    issue(1);

    float acc[4][4][4];
#pragma unroll
    for (int i = 0; i < 4; i++)
#pragma unroll
        for (int j = 0; j < 4; j++)
#pragma unroll
            for (int k = 0; k < 4; k++) acc[i][j][k] = 0.f;

    int sub = lane >> 3, ri = lane & 7;
    int rsel = ((sub & 1) << 3) + ri;      // row offset within 16-row frag
    int csel = (sub >> 1) << 4;            // 0 or 16 bytes (k half)

    for (int h = 0; h < 12; h++) {
        // FIX: final iteration has only its own group pending — must drain
        // to 0, otherwise stage (11%3) is read while group 11 is in flight.
        if (h == 11)
            asm volatile("cp.async.wait_group 0;" ::: "memory");
        else
            asm volatile("cp.async.wait_group 1;" ::: "memory");
        __syncthreads();
        uint32_t sa = su + (h % 3) * ST_BYTES;
        uint32_t sb = sa + 16384;
#pragma unroll
        for (int ks = 0; ks < 4; ks++) {
            int kb = ks * 32;
            uint32_t af[4][4];
#pragma unroll
            for (int mt = 0; mt < 4; mt++) {
                int r = wm * 64 + mt * 16 + rsel;
                int bc = kb + csel;
                uint32_t ad = sa + (uint32_t)r * 128
                            + ((uint32_t)bc ^ ((uint32_t)ri << 4));
                ldsm_x4(af[mt], ad);
            }
            uint32_t bfr[4][2];
#pragma unroll
            for (int p = 0; p < 2; p++) {
                int r = wn * 32 + p * 16 + rsel;
                int bc = kb + csel;
                uint32_t ad = sb + (uint32_t)r * 128
                            + ((uint32_t)bc ^ ((uint32_t)ri << 4));
                uint32_t q[4];
                ldsm_x4(q, ad);
                bfr[2*p][0]   = q[0]; bfr[2*p][1]   = q[2];
                bfr[2*p+1][0] = q[1]; bfr[2*p+1][1] = q[3];
            }
#pragma unroll
            for (int mt = 0; mt < 4; mt++)
#pragma unroll
                for (int nt = 0; nt < 4; nt++) {
                    asm volatile(
                        "mma.sync.aligned.m16n8k16.row.col.f32.bf16.bf16.f32 "
                        "{%0,%1,%2,%3}, {%4,%5,%6,%7}, {%8,%9}, {%0,%1,%2,%3};"
                        : "+f"(acc[mt][nt][0]), "+f"(acc[mt][nt][1]),
                          "+f"(acc[mt][nt][2]), "+f"(acc[mt][nt][3])
                        : "r"(af[mt][0]), "r"(af[mt][1]),
                          "r"(af[mt][2]), "r"(af[mt][3]),
                          "r"(bfr[nt][0]), "r"(bfr[nt][1]));
                }
        }
        if (h + 2 < 12) issue(h + 2);
    }

    // ---- epilogue: bias, store, fused BN stats ----
    int g4 = lane >> 2, t4 = lane & 3;
    float bias2[4][2];
#pragma unroll
    for (int nt = 0; nt < 4; nt++) {
        int nc = wn * 32 + nt * 8 + 2 * t4;
        bias2[nt][0] = biasS[nc];
        bias2[nt][1] = biasS[nc + 1];
    }
    float cs[4][2], cq[4][2];
#pragma unroll
    for (int nt = 0; nt < 4; nt++) { cs[nt][0]=0.f; cs[nt][1]=0.f; cq[nt][0]=0.f; cq[nt][1]=0.f; }
#pragma unroll
    for (int mt = 0; mt < 4; mt++) {
        int r0 = row0 + wm * 64 + mt * 16 + g4;
        int r1 = r0 + 8;
#pragma unroll
        for (int nt = 0; nt < 4; nt++) {
            int nc = wn * 32 + nt * 8 + 2 * t4;
            if (r0 < NN) {
                float v0 = acc[mt][nt][0] + bias2[nt][0];
                float v1 = acc[mt][nt][1] + bias2[nt][1];
                *(float2*)(C + (size_t)r0 * 128 + nc) = make_float2(v0, v1);
                cs[nt][0] += v0; cq[nt][0] += v0 * v0;
                cs[nt][1] += v1; cq[nt][1] += v1 * v1;
            }
            if (r1 < NN) {
                float v2 = acc[mt][nt][2] + bias2[nt][0];
                float v3 = acc[mt][nt][3] + bias2[nt][1];
                *(float2*)(C + (size_t)r1 * 128 + nc) = make_float2(v2, v3);
                cs[nt][0] += v2; cq[nt][0] += v2 * v2;
                cs[nt][1] += v3; cq[nt][1] += v3 * v3;
            }
        }
    }
    __syncthreads();
#pragma unroll
    for (int nt = 0; nt < 4; nt++) {
        int nc = wn * 32 + nt * 8 + 2 * t4;
        atomicAdd(&redS[nc],     cs[nt][0]);
        atomicAdd(&redS[nc + 1], cs[nt][1]);
        atomicAdd(&redQ[nc],     cq[nt][0]);
        atomicAdd(&redQ[nc + 1], cq[nt][1]);
    }
    __syncthreads();
    if (tid < 128) {
        atomicAdd(&g_colsum[tid], redS[tid]);
        atomicAdd(&g_colsq[tid],  redQ[tid]);
    }
}

// ---------------- BN stat helpers -----------------------------------------
__global__ void k_zero_stats() {
    int i = threadIdx.x;
    g_colsum[i] = 0.f; g_colsq[i] = 0.f;
}

__global__ void k_finalize(const float* __restrict__ gamma,
                           const float* __restrict__ beta) {
    int c = threadIdx.x;
    float mu  = g_colsum[c] / (float)NN;
    float var = g_colsq[c] / (float)NN - mu * mu;
    float r = rsqrtf(var + 1e-5f);
    float sc = gamma[c] * r;
    g_scale[c] = sc;
    g_shift[c] = beta[c] - mu * sc;
}

// ---------------- BN apply + ReLU + dropout (+ optional bf16 split) -------
__global__ void k_apply(const float* __restrict__ Y, float* __restrict__ H,
                        int keyidx, int writeSplit) {
    int t = blockIdx.x * blockDim.x + threadIdx.x;
    size_t base = (size_t)t * 4;
    if (base >= (size_t)NN * DD) return;
    uint2 key = g_keys[keyidx];
    float4 v  = *(const float4*)(Y + base);
    int col0  = (int)(base & 127);
    float4 sc = *(const float4*)(g_scale + col0);
    float4 sh = *(const float4*)(g_shift + col0);
    float vv[4]  = {v.x, v.y, v.z, v.w};
    float scv[4] = {sc.x, sc.y, sc.z, sc.w};
    float shv[4] = {sh.x, sh.y, sh.z, sh.w};
    float o[4];
#pragma unroll
    for (int j = 0; j < 4; j++) {
        float val = fmaxf(vv[j] * scv[j] + shv[j], 0.f);
        uint2 r = threefry(key.x, key.y, 0u, (uint32_t)(base + j));
        uint32_t bits = r.x ^ r.y;
        o[j] = (bits & 0x80000000u) ? 0.f : val * 2.f;
    }
    *(float4*)(H + base) = make_float4(o[0], o[1], o[2], o[3]);
    if (writeSplit) {
#pragma unroll
        for (int j = 0; j < 4; j++) {
            __nv_bfloat16 h = __float2bfloat16(o[j]);
            __nv_bfloat16 l = __float2bfloat16(o[j] - __bfloat162float(h));
            g_Hh[base + j] = h;
            g_Hl[base + j] = l;
        }
    }
}

// ---------------- layer 3: P = h@W3l, S = h@W3r + b3 -----------------------
__global__ void k_gemm3(const float* __restrict__ Hin,
                        const float* __restrict__ W3l,
                        const float* __restrict__ W3r,
                        const float* __restrict__ b3) {
    __shared__ float Ws[128 * 32];
    for (int i = threadIdx.x; i < 128 * 16; i += 256) {
        int k = i >> 4, c = i & 15;
        Ws[k * 32 + c]      = W3l[i];
        Ws[k * 32 + 16 + c] = W3r[i];
    }
    __syncthreads();
    int row = blockIdx.x * 8 + (threadIdx.x >> 5);
    int col = threadIdx.x & 31;
    if (row >= NN) return;
    const float* h = Hin + (size_t)row * DD;
    float acc = 0.f;
#pragma unroll 8
    for (int k = 0; k < 128; k += 4) {
        float4 hv = *(const float4*)(h + k);
        acc += hv.x * Ws[(k + 0) * 32 + col];
        acc += hv.y * Ws[(k + 1) * 32 + col];
        acc += hv.z * Ws[(k + 2) * 32 + col];
        acc += hv.w * Ws[(k + 3) * 32 + col];
    }
    if (col >= 16) acc += b3[col - 16];
    g_PS[(size_t)row * 32 + col] = acc;
}

__global__ void k_aggout(float* __restrict__ out) {
    int t = blockIdx.x * blockDim.x + threadIdx.x;
    int node = t >> 4, c = t & 15;
    if (node >= NN) return;
    int s0 = g_rowptr[node], s1 = g_rowptr[node + 1];
    float acc = 0.f;
    int e = s0;
    for (; e + 2 <= s1; e += 2) {
        int a = g_csrsrc[e], b = g_csrsrc[e + 1];
        acc += g_PS[(size_t)a * 32 + c] + g_PS[(size_t)b * 32 + c];
    }
    for (; e < s1; e++) acc += g_PS[(size_t)g_csrsrc[e] * 32 + c];
    out[node * 16 + c] = acc / fmaxf((float)(s1 - s0), 1.f)
                       + g_PS[(size_t)node * 32 + 16 + c];
}

// ---------------- launch ---------------------------------------------------
extern "C" void kernel_launch(void* const* d_in, const int* in_sizes, int n_in,
                              void* d_out, int out_size) {
    const float* x   = (const float*)d_in[0];
    const int*   ei  = (const int*)d_in[1];
    const int*   src = ei;
    const int*   dst = ei + EE;
    const float* W1l = (const float*)d_in[2];
    const float* W1r = (const float*)d_in[3];
    const float* b1  = (const float*)d_in[4];
    const float* g1  = (const float*)d_in[5];
    const float* be1 = (const float*)d_in[6];
    const float* W2l = (const float*)d_in[7];
    const float* W2r = (const float*)d_in[8];
    const float* b2  = (const float*)d_in[9];
    const float* g2  = (const float*)d_in[10];
    const float* be2 = (const float*)d_in[11];
    const float* W3l = (const float*)d_in[12];
    const float* W3r = (const float*)d_in[13];
    const float* b3  = (const float*)d_in[14];
    float* out = (float*)d_out;

    void *pY, *pH, *pMh, *pMl, *pXh, *pXl, *pHh, *pHl, *pWt1, *pWt2;
    cudaGetSymbolAddress(&pY,  g_Y);
    cudaGetSymbolAddress(&pH,  g_H);
    cudaGetSymbolAddress(&pMh, g_Mh);
    cudaGetSymbolAddress(&pMl, g_Ml);
    cudaGetSymbolAddress(&pXh, g_Xh);
    cudaGetSymbolAddress(&pXl, g_Xl);
    cudaGetSymbolAddress(&pHh, g_Hh);
    cudaGetSymbolAddress(&pHl, g_Hl);
    cudaGetSymbolAddress(&pWt1, g_Wt1);
    cudaGetSymbolAddress(&pWt2, g_Wt2);

    cudaFuncSetAttribute(k_mma, cudaFuncAttributeMaxDynamicSharedMemorySize,
                         SM_TOT);

    k_zero_deg<<<(NN + 255) / 256, 256>>>();
    k_keys<<<1, 32>>>();
    k_cvt_w<<<384, 256>>>(W1l, W1r, (__nv_bfloat16*)pWt1);
    k_cvt_w<<<384, 256>>>(W2l, W2r, (__nv_bfloat16*)pWt2);
    k_cvt_x<<<(NN * DD / 4 + 255) / 256, 256>>>(x);
    k_deg<<<EE / 256, 256>>>(dst);
    k_scan1<<<SCAN_B, 1024>>>();
    k_scan2<<<1, 128>>>();
    k_scan3<<<SCAN_B, 1024>>>();
    k_fill<<<EE / 256, 256>>>(src, dst);

    int gemm_grid = (NN + 127) / 128;   // 782

    // layer 1
    k_agg<<<NN / 8, 256>>>(x);
    k_zero_stats<<<1, 128>>>();
    k_mma<<<gemm_grid, 256, SM_TOT>>>(
        (const __nv_bfloat16*)pMh, (const __nv_bfloat16*)pMl,
        (const __nv_bfloat16*)pXh, (const __nv_bfloat16*)pXl,
        (const __nv_bfloat16*)pWt1, b1, (float*)pY);
    k_finalize<<<1, 128>>>(g1, be1);
    k_apply<<<(NN * DD / 4 + 255) / 256, 256>>>((const float*)pY, (float*)pH, 0, 1);

    // layer 2
    k_agg<<<NN / 8, 256>>>((const float*)pH);
    k_zero_stats<<<1, 128>>>();
    k_mma<<<gemm_grid, 256, SM_TOT>>>(
        (const __nv_bfloat16*)pMh, (const __nv_bfloat16*)pMl,
        (const __nv_bfloat16*)pHh, (const __nv_bfloat16*)pHl,
        (const __nv_bfloat16*)pWt2, b2, (float*)pY);
    k_finalize<<<1, 128>>>(g2, be2);
    k_apply<<<(NN * DD / 4 + 255) / 256, 256>>>((const float*)pY, (float*)pH, 1, 0);

    // layer 3 (transform-then-aggregate)
    k_gemm3<<<(NN + 7) / 8, 256>>>((const float*)pH, W3l, W3r, b3);
    k_aggout<<<NN * 16 / 256, 256>>>(out);
}

// round 11
// speedup vs baseline: 1.6111x; 1.1584x over previous
#include <cuda_runtime.h>
#include <cuda_bf16.h>
#include <stdint.h>

#define NN 100000
#define DD 128
#define EE 1600000
#define SCAN_B 98   // ceil(NN/1024)

// ---------------- scratch (device globals: no allocation allowed) ----------
__device__ __align__(16) float g_Y[(size_t)NN*DD];   // pre-BN linear output
__device__ __align__(16) float g_H[(size_t)NN*DD];   // post-activation features
__device__ __align__(16) float g_PS[(size_t)NN*32];  // layer3: [P(16) | S(16)]
__device__ __align__(16) __nv_bfloat16 g_Mh[(size_t)NN*DD];  // mean hi
__device__ __align__(16) __nv_bfloat16 g_Ml[(size_t)NN*DD];  // mean lo
__device__ __align__(16) __nv_bfloat16 g_Xh[(size_t)NN*DD];  // x hi
__device__ __align__(16) __nv_bfloat16 g_Xl[(size_t)NN*DD];  // x lo
__device__ __align__(16) __nv_bfloat16 g_Hh[(size_t)NN*DD];  // h hi
__device__ __align__(16) __nv_bfloat16 g_Hl[(size_t)NN*DD];  // h lo
__device__ __align__(16) __nv_bfloat16 g_Wt1[128*768];       // layer1 weights, [n][k]
__device__ __align__(16) __nv_bfloat16 g_Wt2[128*768];       // layer2 weights, [n][k]
__device__ int g_deg[NN];
__device__ int g_rowptr[NN+1];
__device__ int g_cursor[NN];
__device__ int g_csrsrc[EE];
__device__ int g_bsum[SCAN_B];
__device__ int g_boff[SCAN_B];
__device__ __align__(16) float g_colsum[2][DD];
__device__ __align__(16) float g_colsq[2][DD];
__device__ __align__(16) float g_scale[DD];
__device__ __align__(16) float g_shift[DD];
__device__ uint2 g_keys[2];

// ---------------- threefry2x32 (matches JAX) ------------------------------
__device__ __forceinline__ uint32_t rotl32(uint32_t v, int d) {
    return (v << d) | (v >> (32 - d));
}

__device__ __forceinline__ uint2 threefry(uint32_t k0, uint32_t k1,
                                          uint32_t x0, uint32_t x1) {
    uint32_t k2 = k0 ^ k1 ^ 0x1BD11BDAu;
    x0 += k0; x1 += k1;
#define TFR(a,b,c,d) \
    x0+=x1; x1=rotl32(x1,a); x1^=x0; \
    x0+=x1; x1=rotl32(x1,b); x1^=x0; \
    x0+=x1; x1=rotl32(x1,c); x1^=x0; \
    x0+=x1; x1=rotl32(x1,d); x1^=x0;
    TFR(13,15,26,6)   x0+=k1; x1+=k2+1u;
    TFR(17,29,16,24)  x0+=k2; x1+=k0+2u;
    TFR(13,15,26,6)   x0+=k0; x1+=k1+3u;
    TFR(17,29,16,24)  x0+=k1; x1+=k2+4u;
    TFR(13,15,26,6)   x0+=k2; x1+=k0+5u;
#undef TFR
    return make_uint2(x0, x1);
}

// ---------------- fused init: zero deg, keys, zero both stat buffers -------
__global__ void k_init() {
    int i = blockIdx.x * blockDim.x + threadIdx.x;
    if (i < NN) g_deg[i] = 0;
    if (blockIdx.x == 0) {
        if (threadIdx.x == 0) {
            g_keys[0] = threefry(0u, 42u, 0u, 0u);
            g_keys[1] = threefry(0u, 42u, 0u, 1u);
        }
        if (threadIdx.x < 128) {
            g_colsum[0][threadIdx.x] = 0.f; g_colsq[0][threadIdx.x] = 0.f;
            g_colsum[1][threadIdx.x] = 0.f; g_colsq[1][threadIdx.x] = 0.f;
        }
    }
}

// ---------------- CSR build ------------------------------------------------
__global__ void k_deg(const int* __restrict__ dst) {
    int e = blockIdx.x * blockDim.x + threadIdx.x;
    if (e < EE) atomicAdd(&g_deg[dst[e]], 1);
}

__global__ void k_scan1() {
    __shared__ int sh[1024];
    int tid = threadIdx.x;
    int i = blockIdx.x * 1024 + tid;
    int v = (i < NN) ? g_deg[i] : 0;
    sh[tid] = v;
    __syncthreads();
    for (int off = 1; off < 1024; off <<= 1) {
        int t = (tid >= off) ? sh[tid - off] : 0;
        __syncthreads();
        sh[tid] += t;
        __syncthreads();
    }
    if (i < NN) g_rowptr[i] = sh[tid] - v;
    if (tid == 1023) g_bsum[blockIdx.x] = sh[1023];
}

__global__ void k_scan2() {
    __shared__ int sh[128];
    int tid = threadIdx.x;
    int v = (tid < SCAN_B) ? g_bsum[tid] : 0;
    sh[tid] = v;
    __syncthreads();
    for (int off = 1; off < 128; off <<= 1) {
        int t = (tid >= off) ? sh[tid - off] : 0;
        __syncthreads();
        sh[tid] += t;
        __syncthreads();
    }
    if (tid < SCAN_B) g_boff[tid] = sh[tid] - v;
    if (tid == 127) g_rowptr[NN] = sh[127];
}

__global__ void k_scan3() {
    int i = blockIdx.x * blockDim.x + threadIdx.x;
    if (i < NN) {
        int r = g_rowptr[i] + g_boff[i >> 10];
        g_rowptr[i] = r;
        g_cursor[i] = r;
    }
}

__global__ void k_fill(const int* __restrict__ src, const int* __restrict__ dst) {
    int e = blockIdx.x * blockDim.x + threadIdx.x;
    if (e < EE) {
        int p = atomicAdd(&g_cursor[dst[e]], 1);
        g_csrsrc[p] = src[e];
    }
}

// ---------------- mean aggregation (warp per node) → bf16 hi/lo -----------
__global__ void k_agg(const float* __restrict__ X) {
    int w = (blockIdx.x * blockDim.x + threadIdx.x) >> 5;
    int lane = threadIdx.x & 31;
    if (w >= NN) return;
    int s0 = g_rowptr[w], s1 = g_rowptr[w + 1];
    float4 acc = make_float4(0.f, 0.f, 0.f, 0.f);
    int e = s0;
    for (; e + 4 <= s1; e += 4) {
        int a = g_csrsrc[e], b = g_csrsrc[e+1], c = g_csrsrc[e+2], d = g_csrsrc[e+3];
        float4 va = *(const float4*)(X + (size_t)a * DD + lane * 4);
        float4 vb = *(const float4*)(X + (size_t)b * DD + lane * 4);
        float4 vc = *(const float4*)(X + (size_t)c * DD + lane * 4);
        float4 vd = *(const float4*)(X + (size_t)d * DD + lane * 4);
        acc.x += va.x + vb.x + vc.x + vd.x;
        acc.y += va.y + vb.y + vc.y + vd.y;
        acc.z += va.z + vb.z + vc.z + vd.z;
        acc.w += va.w + vb.w + vc.w + vd.w;
    }
    for (; e < s1; e++) {
        int a = g_csrsrc[e];
        float4 va = *(const float4*)(X + (size_t)a * DD + lane * 4);
        acc.x += va.x; acc.y += va.y; acc.z += va.z; acc.w += va.w;
    }
    float inv = 1.f / fmaxf((float)(s1 - s0), 1.f);
    float m[4] = {acc.x * inv, acc.y * inv, acc.z * inv, acc.w * inv};
    size_t base = (size_t)w * DD + lane * 4;
#pragma unroll
    for (int j = 0; j < 4; j++) {
        __nv_bfloat16 h = __float2bfloat16(m[j]);
        __nv_bfloat16 l = __float2bfloat16(m[j] - __bfloat162float(h));
        g_Mh[base + j] = h;
        g_Ml[base + j] = l;
    }
}

// ---------------- split x into bf16 hi/lo ----------------------------------
__global__ void k_cvt_x(const float* __restrict__ X) {
    int t = blockIdx.x * blockDim.x + threadIdx.x;
    size_t base = (size_t)t * 4;
    if (base >= (size_t)NN * DD) return;
    float4 v = *(const float4*)(X + base);
    float m[4] = {v.x, v.y, v.z, v.w};
#pragma unroll
    for (int j = 0; j < 4; j++) {
        __nv_bfloat16 h = __float2bfloat16(m[j]);
        __nv_bfloat16 l = __float2bfloat16(m[j] - __bfloat162float(h));
        g_Xh[base + j] = h;
        g_Xl[base + j] = l;
    }
}

// ---------------- build transposed split weights Wt[n][768] ----------------
// logical K rows: [Wl_h | Wl_l | Wl_h | Wr_h | Wr_l | Wr_h]
__global__ void k_cvt_w(const float* __restrict__ Wl, const float* __restrict__ Wr,
                        __nv_bfloat16* __restrict__ Wt) {
    int idx = blockIdx.x * blockDim.x + threadIdx.x;   // 0..98303
    if (idx >= 768 * 128) return;
    int n = idx & 127;
    int rr = idx >> 7;          // 0..767
    int seg = rr >> 7, kk = rr & 127;
    const float* src = (seg < 3) ? Wl : Wr;
    float w = src[kk * 128 + n];
    __nv_bfloat16 h = __float2bfloat16(w);
    __nv_bfloat16 l = __float2bfloat16(w - __bfloat162float(h));
    bool lopart = (seg == 1 || seg == 4);
    Wt[(size_t)n * 768 + rr] = lopart ? l : h;
}

// ================= helpers ================================================
__device__ __forceinline__ uint32_t s2u(const void* p) {
    uint32_t a;
    asm("{ .reg .u64 t; cvta.to.shared.u64 t, %1; cvt.u32.u64 %0, t; }"
        : "=r"(a) : "l"(p));
    return a;
}

__device__ __forceinline__ void cp_async16(uint32_t saddr, const void* gaddr, int sz) {
    asm volatile("cp.async.cg.shared.global [%0], [%1], 16, %2;"
                 :: "r"(saddr), "l"(gaddr), "r"(sz));
}

__device__ __forceinline__ void ldsm_x4(uint32_t* r, uint32_t addr) {
    asm volatile("ldmatrix.sync.aligned.m8n8.x4.shared.b16 {%0,%1,%2,%3}, [%4];"
                 : "=r"(r[0]), "=r"(r[1]), "=r"(r[2]), "=r"(r[3]) : "r"(addr));
}

// smem: 3 stages x (A 16KB + B 16KB) + aux
#define ST_BYTES 32768
#define SM_BIAS  98304
#define SM_RS    (98304 + 512)
#define SM_RQ    (98304 + 1024)
#define SM_TOT   (98304 + 1536)

// ---------------- HMMA GEMM: C[128r,128c] = A[128,768] @ Wt^T + bias -------
// 12 K-chunks of 64: A source = {Mh,Mh,Ml,Bh,Bh,Bl}[h>>1], col (h&1)*64
// NOTE: 2 CTAs/SM (192KB smem of 228KB) — discriminates latency- vs
// throughput-bound HMMA.
__global__ __launch_bounds__(256, 2)
void k_mma(const __nv_bfloat16* __restrict__ Ah,
           const __nv_bfloat16* __restrict__ Al,
           const __nv_bfloat16* __restrict__ Bh,
           const __nv_bfloat16* __restrict__ Bl,
           const __nv_bfloat16* __restrict__ Wt,
           const float* __restrict__ bias,
           float* __restrict__ C,
           float* __restrict__ colsum,
           float* __restrict__ colsq) {
    extern __shared__ __align__(128) char smem[];
    uint32_t su = s2u(smem);
    int tid  = threadIdx.x;
    int lane = tid & 31;
    int warp = tid >> 5;
    int wm = warp & 1;          // 2 warps over M (64 rows)
    int wn = warp >> 1;         // 4 warps over N (32 cols)
    int row0 = blockIdx.x * 128;

    float* biasS = (float*)(smem + SM_BIAS);
    float* redS  = (float*)(smem + SM_RS);
    float* redQ  = (float*)(smem + SM_RQ);
    if (tid < 128) { biasS[tid] = bias[tid]; redS[tid] = 0.f; redQ[tid] = 0.f; }

    // issue one stage's cp.async group (A tile + B tile, 128x64 bf16 each)
    auto issue = [&](int h) {
        int c = h >> 1;
        const __nv_bfloat16* Asrc =
            (c <= 1) ? Ah : (c == 2) ? Al : (c <= 4) ? Bh : Bl;
        int acol = (h & 1) * 64;
        uint32_t sa = su + (h % 3) * ST_BYTES;
        uint32_t sb = sa + 16384;
#pragma unroll
        for (int t = 0; t < 4; t++) {
            int q = tid + t * 256;          // 0..1023
            int r = q >> 3, g = q & 7;
            uint32_t off = (uint32_t)r * 128 + (((uint32_t)g << 4) ^ ((uint32_t)(r & 7) << 4));
            bool live = (row0 + r) < NN;
            const __nv_bfloat16* gA =
                Asrc + (live ? ((size_t)(row0 + r) * 128 + acol + g * 8) : 0);
            cp_async16(sa + off, gA, live ? 16 : 0);
            const __nv_bfloat16* gB = Wt + (size_t)r * 768 + h * 64 + g * 8;
            cp_async16(sb + off, gB, 16);
        }
        asm volatile("cp.async.commit_group;" ::: "memory");
    };

    issue(0);
    issue(1);

    float acc[4][4][4];
#pragma unroll
    for (int i = 0; i < 4; i++)
#pragma unroll
        for (int j = 0; j < 4; j++)
#pragma unroll
            for (int k = 0; k < 4; k++) acc[i][j][k] = 0.f;

    int sub = lane >> 3, ri = lane & 7;
    int rsel = ((sub & 1) << 3) + ri;      // row offset within 16-row frag
    int csel = (sub >> 1) << 4;            // 0 or 16 bytes (k half)

    for (int h = 0; h < 12; h++) {
        // final iteration: only its own group pending — drain fully
        if (h == 11)
            asm volatile("cp.async.wait_group 0;" ::: "memory");
        else
            asm volatile("cp.async.wait_group 1;" ::: "memory");
        __syncthreads();
        uint32_t sa = su + (h % 3) * ST_BYTES;
        uint32_t sb = sa + 16384;
#pragma unroll
        for (int ks = 0; ks < 4; ks++) {
            int kb = ks * 32;
            uint32_t af[4][4];
#pragma unroll
            for (int mt = 0; mt < 4; mt++) {
                int r = wm * 64 + mt * 16 + rsel;
                int bc = kb + csel;
                uint32_t ad = sa + (uint32_t)r * 128
                            + ((uint32_t)bc ^ ((uint32_t)ri << 4));
                ldsm_x4(af[mt], ad);
            }
            uint32_t bfr[4][2];
#pragma unroll
            for (int p = 0; p < 2; p++) {
                int r = wn * 32 + p * 16 + rsel;
                int bc = kb + csel;
                uint32_t ad = sb + (uint32_t)r * 128
                            + ((uint32_t)bc ^ ((uint32_t)ri << 4));
                uint32_t q[4];
                ldsm_x4(q, ad);
                bfr[2*p][0]   = q[0]; bfr[2*p][1]   = q[2];
                bfr[2*p+1][0] = q[1]; bfr[2*p+1][1] = q[3];
            }
#pragma unroll
            for (int mt = 0; mt < 4; mt++)
#pragma unroll
                for (int nt = 0; nt < 4; nt++) {
                    asm volatile(
                        "mma.sync.aligned.m16n8k16.row.col.f32.bf16.bf16.f32 "
                        "{%0,%1,%2,%3}, {%4,%5,%6,%7}, {%8,%9}, {%0,%1,%2,%3};"
                        : "+f"(acc[mt][nt][0]), "+f"(acc[mt][nt][1]),
                          "+f"(acc[mt][nt][2]), "+f"(acc[mt][nt][3])
                        : "r"(af[mt][0]), "r"(af[mt][1]),
                          "r"(af[mt][2]), "r"(af[mt][3]),
                          "r"(bfr[nt][0]), "r"(bfr[nt][1]));
                }
        }
        if (h + 2 < 12) issue(h + 2);
    }

    // ---- epilogue: bias, store, fused BN stats ----
    int g4 = lane >> 2, t4 = lane & 3;
    float bias2[4][2];
#pragma unroll
    for (int nt = 0; nt < 4; nt++) {
        int nc = wn * 32 + nt * 8 + 2 * t4;
        bias2[nt][0] = biasS[nc];
        bias2[nt][1] = biasS[nc + 1];
    }
    float cs[4][2], cq[4][2];
#pragma unroll
    for (int nt = 0; nt < 4; nt++) { cs[nt][0]=0.f; cs[nt][1]=0.f; cq[nt][0]=0.f; cq[nt][1]=0.f; }
#pragma unroll
    for (int mt = 0; mt < 4; mt++) {
        int r0 = row0 + wm * 64 + mt * 16 + g4;
        int r1 = r0 + 8;
#pragma unroll
        for (int nt = 0; nt < 4; nt++) {
            int nc = wn * 32 + nt * 8 + 2 * t4;
            if (r0 < NN) {
                float v0 = acc[mt][nt][0] + bias2[nt][0];
                float v1 = acc[mt][nt][1] + bias2[nt][1];
                *(float2*)(C + (size_t)r0 * 128 + nc) = make_float2(v0, v1);
                cs[nt][0] += v0; cq[nt][0] += v0 * v0;
                cs[nt][1] += v1; cq[nt][1] += v1 * v1;
            }
            if (r1 < NN) {
                float v2 = acc[mt][nt][2] + bias2[nt][0];
                float v3 = acc[mt][nt][3] + bias2[nt][1];
                *(float2*)(C + (size_t)r1 * 128 + nc) = make_float2(v2, v3);
                cs[nt][0] += v2; cq[nt][0] += v2 * v2;
                cs[nt][1] += v3; cq[nt][1] += v3 * v3;
            }
        }
    }
    __syncthreads();
#pragma unroll
    for (int nt = 0; nt < 4; nt++) {
        int nc = wn * 32 + nt * 8 + 2 * t4;
        atomicAdd(&redS[nc],     cs[nt][0]);
        atomicAdd(&redS[nc + 1], cs[nt][1]);
        atomicAdd(&redQ[nc],     cq[nt][0]);
        atomicAdd(&redQ[nc + 1], cq[nt][1]);
    }
    __syncthreads();
    if (tid < 128) {
        atomicAdd(&colsum[tid], redS[tid]);
        atomicAdd(&colsq[tid],  redQ[tid]);
    }
}

// ---------------- BN finalize ----------------------------------------------
__global__ void k_finalize(const float* __restrict__ gamma,
                           const float* __restrict__ beta, int layer) {
    int c = threadIdx.x;
    float mu  = g_colsum[layer][c] / (float)NN;
    float var = g_colsq[layer][c] / (float)NN - mu * mu;
    float r = rsqrtf(var + 1e-5f);
    float sc = gamma[c] * r;
    g_scale[c] = sc;
    g_shift[c] = beta[c] - mu * sc;
}

// ---------------- BN apply + ReLU + dropout (+ optional bf16 split) -------
__global__ void k_apply(const float* __restrict__ Y, float* __restrict__ H,
                        int keyidx, int writeSplit) {
    int t = blockIdx.x * blockDim.x + threadIdx.x;
    size_t base = (size_t)t * 4;
    if (base >= (size_t)NN * DD) return;
    uint2 key = g_keys[keyidx];
    float4 v  = *(const float4*)(Y + base);
    int col0  = (int)(base & 127);
    float4 sc = *(const float4*)(g_scale + col0);
    float4 sh = *(const float4*)(g_shift + col0);
    float vv[4]  = {v.x, v.y, v.z, v.w};
    float scv[4] = {sc.x, sc.y, sc.z, sc.w};
    float shv[4] = {sh.x, sh.y, sh.z, sh.w};
    float o[4];
#pragma unroll
    for (int j = 0; j < 4; j++) {
        float val = fmaxf(vv[j] * scv[j] + shv[j], 0.f);
        uint2 r = threefry(key.x, key.y, 0u, (uint32_t)(base + j));
        uint32_t bits = r.x ^ r.y;
        o[j] = (bits & 0x80000000u) ? 0.f : val * 2.f;
    }
    *(float4*)(H + base) = make_float4(o[0], o[1], o[2], o[3]);
    if (writeSplit) {
#pragma unroll
        for (int j = 0; j < 4; j++) {
            __nv_bfloat16 h = __float2bfloat16(o[j]);
            __nv_bfloat16 l = __float2bfloat16(o[j] - __bfloat162float(h));
            g_Hh[base + j] = h;
            g_Hl[base + j] = l;
        }
    }
}

// ---------------- layer 3: P = h@W3l, S = h@W3r + b3 -----------------------
__global__ void k_gemm3(const float* __restrict__ Hin,
                        const float* __restrict__ W3l,
                        const float* __restrict__ W3r,
                        const float* __restrict__ b3) {
    __shared__ float Ws[128 * 32];
    for (int i = threadIdx.x; i < 128 * 16; i += 256) {
        int k = i >> 4, c = i & 15;
        Ws[k * 32 + c]      = W3l[i];
        Ws[k * 32 + 16 + c] = W3r[i];
    }
    __syncthreads();
    int row = blockIdx.x * 8 + (threadIdx.x >> 5);
    int col = threadIdx.x & 31;
    if (row >= NN) return;
    const float* h = Hin + (size_t)row * DD;
    float acc = 0.f;
#pragma unroll 8
    for (int k = 0; k < 128; k += 4) {
        float4 hv = *(const float4*)(h + k);
        acc += hv.x * Ws[(k + 0) * 32 + col];
        acc += hv.y * Ws[(k + 1) * 32 + col];
        acc += hv.z * Ws[(k + 2) * 32 + col];
        acc += hv.w * Ws[(k + 3) * 32 + col];
    }
    if (col >= 16) acc += b3[col - 16];
    g_PS[(size_t)row * 32 + col] = acc;
}

__global__ void k_aggout(float* __restrict__ out) {
    int t = blockIdx.x * blockDim.x + threadIdx.x;
    int node = t >> 4, c = t & 15;
    if (node >= NN) return;
    int s0 = g_rowptr[node], s1 = g_rowptr[node + 1];
    float acc = 0.f;
    int e = s0;
    for (; e + 2 <= s1; e += 2) {
        int a = g_csrsrc[e], b = g_csrsrc[e + 1];
        acc += g_PS[(size_t)a * 32 + c] + g_PS[(size_t)b * 32 + c];
    }
    for (; e < s1; e++) acc += g_PS[(size_t)g_csrsrc[e] * 32 + c];
    out[node * 16 + c] = acc / fmaxf((float)(s1 - s0), 1.f)
                       + g_PS[(size_t)node * 32 + 16 + c];
}

// ---------------- launch ---------------------------------------------------
extern "C" void kernel_launch(void* const* d_in, const int* in_sizes, int n_in,
                              void* d_out, int out_size) {
    const float* x   = (const float*)d_in[0];
    const int*   ei  = (const int*)d_in[1];
    const int*   src = ei;
    const int*   dst = ei + EE;
    const float* W1l = (const float*)d_in[2];
    const float* W1r = (const float*)d_in[3];
    const float* b1  = (const float*)d_in[4];
    const float* g1  = (const float*)d_in[5];
    const float* be1 = (const float*)d_in[6];
    const float* W2l = (const float*)d_in[7];
    const float* W2r = (const float*)d_in[8];
    const float* b2  = (const float*)d_in[9];
    const float* g2  = (const float*)d_in[10];
    const float* be2 = (const float*)d_in[11];
    const float* W3l = (const float*)d_in[12];
    const float* W3r = (const float*)d_in[13];
    const float* b3  = (const float*)d_in[14];
    float* out = (float*)d_out;

    void *pY, *pH, *pMh, *pMl, *pXh, *pXl, *pHh, *pHl, *pWt1, *pWt2, *pCS, *pCQ;
    cudaGetSymbolAddress(&pY,  g_Y);
    cudaGetSymbolAddress(&pH,  g_H);
    cudaGetSymbolAddress(&pMh, g_Mh);
    cudaGetSymbolAddress(&pMl, g_Ml);
    cudaGetSymbolAddress(&pXh, g_Xh);
    cudaGetSymbolAddress(&pXl, g_Xl);
    cudaGetSymbolAddress(&pHh, g_Hh);
    cudaGetSymbolAddress(&pHl, g_Hl);
    cudaGetSymbolAddress(&pWt1, g_Wt1);
    cudaGetSymbolAddress(&pWt2, g_Wt2);
    cudaGetSymbolAddress(&pCS, g_colsum);
    cudaGetSymbolAddress(&pCQ, g_colsq);

    cudaFuncSetAttribute(k_mma, cudaFuncAttributeMaxDynamicSharedMemorySize,
                         SM_TOT);

    k_init<<<(NN + 255) / 256, 256>>>();
    k_cvt_w<<<384, 256>>>(W1l, W1r, (__nv_bfloat16*)pWt1);
    k_cvt_w<<<384, 256>>>(W2l, W2r, (__nv_bfloat16*)pWt2);
    k_cvt_x<<<(NN * DD / 4 + 255) / 256, 256>>>(x);
    k_deg<<<EE / 256, 256>>>(dst);
    k_scan1<<<SCAN_B, 1024>>>();
    k_scan2<<<1, 128>>>();
    k_scan3<<<SCAN_B, 1024>>>();
    k_fill<<<EE / 256, 256>>>(src, dst);

    int gemm_grid = (NN + 127) / 128;   // 782

    // layer 1
    k_agg<<<NN / 8, 256>>>(x);
    k_mma<<<gemm_grid, 256, SM_TOT>>>(
        (const __nv_bfloat16*)pMh, (const __nv_bfloat16*)pMl,
        (const __nv_bfloat16*)pXh, (const __nv_bfloat16*)pXl,
        (const __nv_bfloat16*)pWt1, b1, (float*)pY,
        (float*)pCS, (float*)pCQ);
    k_finalize<<<1, 128>>>(g1, be1, 0);
    k_apply<<<(NN * DD / 4 + 255) / 256, 256>>>((const float*)pY, (float*)pH, 0, 1);

    // layer 2
    k_agg<<<NN / 8, 256>>>((const float*)pH);
    k_mma<<<gemm_grid, 256, SM_TOT>>>(
        (const __nv_bfloat16*)pMh, (const __nv_bfloat16*)pMl,
        (const __nv_bfloat16*)pHh, (const __nv_bfloat16*)pHl,
        (const __nv_bfloat16*)pWt2, b2, (float*)pY,
        (float*)pCS + DD, (float*)pCQ + DD);
    k_finalize<<<1, 128>>>(g2, be2, 1);
    k_apply<<<(NN * DD / 4 + 255) / 256, 256>>>((const float*)pY, (float*)pH, 1, 0);

    // layer 3 (transform-then-aggregate)
    k_gemm3<<<(NN + 7) / 8, 256>>>((const float*)pH, W3l, W3r, b3);
    k_aggout<<<NN * 16 / 256, 256>>>(out);
}